// round 5
// baseline (speedup 1.0000x reference)
#include <cuda_runtime.h>
#include <cstdint>

#define BATCH   8192
#define DINA    4096
#define DINB    2048
#define DLAT    256
#define NCODE   8192
#define BETA_F  0.25f

// ---------------- scratch (static __device__ — no allocation) ----------------
__device__ float g_ze_a0[BATCH * DLAT];
__device__ float g_ze_a1[BATCH * DLAT];
__device__ float g_ze_b0[BATCH * DLAT];
__device__ float g_ze_b1[BATCH * DLAT];
__device__ float g_h0[2 * BATCH * DLAT];
__device__ float g_h1[2 * BATCH * DLAT];
__device__ double g_zz_a[BATCH];
__device__ double g_zz_b[BATCH];
__device__ unsigned long long g_amin_a[BATCH];
__device__ unsigned long long g_amin_b[BATCH];

// ---------------- small helpers ----------------
__global__ void init_amin_kernel() {
    int i = blockIdx.x * blockDim.x + threadIdx.x;
    if (i < BATCH) { g_amin_a[i] = ~0ull; g_amin_b[i] = ~0ull; }
}

// ||z_row||^2 in fp64 (binade anchor for the rounding grid)
__global__ void zz_kernel(const float* __restrict__ Z, double* __restrict__ zz) {
    int row  = blockIdx.x * 8 + (threadIdx.x >> 5);
    int lane = threadIdx.x & 31;
    const float4* zp = reinterpret_cast<const float4*>(Z) + (size_t)row * (DLAT / 4);
    double s = 0.0;
#pragma unroll
    for (int t = 0; t < 2; t++) {
        float4 v = zp[lane + 32 * t];
        s += (double)v.x * v.x + (double)v.y * v.y
           + (double)v.z * v.z + (double)v.w * v.w;
    }
#pragma unroll
    for (int o = 16; o; o >>= 1) s += __shfl_down_sync(0xffffffffu, s, o);
    if (lane == 0) zz[row] = s;
}

// ---------------- 128x128x8 tile compute: 8x8 microtile, LDS.128 ------------
// Per-output accumulation is a single fp32 FMA chain over ascending k —
// bit-identical to the round-4 kernel (argmin-critical).
template<int BS>
__device__ __forceinline__ void compute_tile(const float (*As)[132],
                                             const float (*Bs)[BS],
                                             int tx, int ty, float acc[8][8])
{
#pragma unroll
    for (int kk = 0; kk < 8; kk++) {
        float a[8], b[8];
        float4 t;
        t = *(const float4*)&As[kk][ty * 4];      a[0]=t.x; a[1]=t.y; a[2]=t.z; a[3]=t.w;
        t = *(const float4*)&As[kk][ty * 4 + 64]; a[4]=t.x; a[5]=t.y; a[6]=t.z; a[7]=t.w;
        t = *(const float4*)&Bs[kk][tx * 4];      b[0]=t.x; b[1]=t.y; b[2]=t.z; b[3]=t.w;
        t = *(const float4*)&Bs[kk][tx * 4 + 64]; b[4]=t.x; b[5]=t.y; b[6]=t.z; b[7]=t.w;
#pragma unroll
        for (int i = 0; i < 8; i++)
#pragma unroll
            for (int j = 0; j < 8; j++)
                acc[i][j] = fmaf(a[i], b[j], acc[i][j]);
    }
}

// ---------------- generic fused GEMM (BM=BN=128, BK=8, double-buffered) -----
// C = [RESID? A +] [RELU?] (A @ W + bias); W row-major [K,N].
// Rows < rowSplit -> C0, else C1 at (row - rowSplit).
template<bool RELU, bool RESID>
__global__ __launch_bounds__(256)
void gemm_kernel(const float* __restrict__ A, const float* __restrict__ W,
                 const float* __restrict__ bias,
                 float* __restrict__ C0, float* __restrict__ C1,
                 int rowSplit, int N, int K)
{
    __shared__ float As[2][8][132];
    __shared__ float Bs[2][8][128];
    const int tid = threadIdx.x;
    const int tx = tid & 15, ty = tid >> 4;
    const int rowBase = blockIdx.y * 128;
    const int colBase = blockIdx.x * 128;

    const int ar = tid >> 1, ac4 = (tid & 1) * 4;     // A: 128 rows x 2 float4
    const int br = tid >> 5, bc = (tid & 31) * 4;     // B: 8 rows x 32 float4
    const float* Ap = A + (size_t)(rowBase + ar) * K + ac4;
    const float* Wp = W + (size_t)br * N + colBase + bc;

    float acc[8][8];
#pragma unroll
    for (int i = 0; i < 8; i++)
#pragma unroll
        for (int j = 0; j < 8; j++) acc[i][j] = 0.f;

    float4 av = *(const float4*)Ap;
    float4 bv = *(const float4*)Wp;
    As[0][ac4 + 0][ar] = av.x; As[0][ac4 + 1][ar] = av.y;
    As[0][ac4 + 2][ar] = av.z; As[0][ac4 + 3][ar] = av.w;
    *(float4*)&Bs[0][br][bc] = bv;
    __syncthreads();

    int buf = 0;
    for (int k0 = 8; k0 < K; k0 += 8) {
        av = *(const float4*)(Ap + k0);
        bv = *(const float4*)(Wp + (size_t)k0 * N);
        compute_tile<128>(As[buf], Bs[buf], tx, ty, acc);
        As[buf ^ 1][ac4 + 0][ar] = av.x; As[buf ^ 1][ac4 + 1][ar] = av.y;
        As[buf ^ 1][ac4 + 2][ar] = av.z; As[buf ^ 1][ac4 + 3][ar] = av.w;
        *(float4*)&Bs[buf ^ 1][br][bc] = bv;
        buf ^= 1;
        __syncthreads();
    }
    compute_tile<128>(As[buf], Bs[buf], tx, ty, acc);

#pragma unroll
    for (int i = 0; i < 8; i++) {
        int row = rowBase + ty * 4 + (i & 3) + (i >> 2) * 64;
        float* cr = (row < rowSplit) ? (C0 + (size_t)row * N)
                                     : (C1 + (size_t)(row - rowSplit) * N);
        const float* rr = RESID ? (A + (size_t)row * K) : nullptr;  // K==N here
#pragma unroll
        for (int g = 0; g < 2; g++) {
            int col = colBase + tx * 4 + g * 64;
            float4 bb = *(const float4*)(bias + col);
            float4 v;
            v.x = acc[i][g * 4 + 0] + bb.x;
            v.y = acc[i][g * 4 + 1] + bb.y;
            v.z = acc[i][g * 4 + 2] + bb.z;
            v.w = acc[i][g * 4 + 3] + bb.w;
            if (RELU) {
                v.x = fmaxf(v.x, 0.f); v.y = fmaxf(v.y, 0.f);
                v.z = fmaxf(v.z, 0.f); v.w = fmaxf(v.w, 0.f);
            }
            if (RESID) {
                float4 rv = *(const float4*)(rr + col);
                v.x += rv.x; v.y += rv.y; v.z += rv.z; v.w += rv.w;
            }
            *(float4*)(cr + col) = v;
        }
    }
}

// ---------------- VQ: fp32-sequential GEMM + rounding-faithful argmin --------
// Same engine (E loaded NT-transposed), identical round-4 epilogue math:
// winner = first k maximizing r_k = cell * rint(t_k / cell), cell = ulp-grid
// of d = zz - t anchored at d's binade (see round-4 derivation).
__global__ __launch_bounds__(256)
void vq_argmin_kernel(const float* __restrict__ Z, const float* __restrict__ E,
                      const double* __restrict__ ZZ,
                      unsigned long long* __restrict__ amin)
{
    __shared__ float As[2][8][132];
    __shared__ float Bs[2][8][132];
    const int tid = threadIdx.x;
    const int tx = tid & 15, ty = tid >> 4;
    const int rowBase = blockIdx.y * 128;
    const int colBase = blockIdx.x * 128;

    const int ar = tid >> 1, ac4 = (tid & 1) * 4;
    const float* Zp = Z + (size_t)(rowBase + ar) * DLAT + ac4;
    const float* Ep = E + (size_t)(colBase + ar) * DLAT + ac4;  // NT: E rows = N dim

    float acc[8][8];
#pragma unroll
    for (int i = 0; i < 8; i++)
#pragma unroll
        for (int j = 0; j < 8; j++) acc[i][j] = 0.f;

    float4 av = *(const float4*)Zp;
    float4 ev = *(const float4*)Ep;
    As[0][ac4 + 0][ar] = av.x; As[0][ac4 + 1][ar] = av.y;
    As[0][ac4 + 2][ar] = av.z; As[0][ac4 + 3][ar] = av.w;
    Bs[0][ac4 + 0][ar] = ev.x; Bs[0][ac4 + 1][ar] = ev.y;
    Bs[0][ac4 + 2][ar] = ev.z; Bs[0][ac4 + 3][ar] = ev.w;
    __syncthreads();

    int buf = 0;
    for (int k0 = 8; k0 < DLAT; k0 += 8) {
        av = *(const float4*)(Zp + k0);
        ev = *(const float4*)(Ep + k0);
        compute_tile<132>(As[buf], Bs[buf], tx, ty, acc);
        As[buf ^ 1][ac4 + 0][ar] = av.x; As[buf ^ 1][ac4 + 1][ar] = av.y;
        As[buf ^ 1][ac4 + 2][ar] = av.z; As[buf ^ 1][ac4 + 3][ar] = av.w;
        Bs[buf ^ 1][ac4 + 0][ar] = ev.x; Bs[buf ^ 1][ac4 + 1][ar] = ev.y;
        Bs[buf ^ 1][ac4 + 2][ar] = ev.z; Bs[buf ^ 1][ac4 + 3][ar] = ev.w;
        buf ^= 1;
        __syncthreads();
    }
    compute_tile<132>(As[buf], Bs[buf], tx, ty, acc);

#pragma unroll
    for (int i = 0; i < 8; i++) {
        int row = rowBase + ty * 4 + (i & 3) + (i >> 2) * 64;
        double zz = ZZ[row];
        unsigned long long best = ~0ull;
#pragma unroll
        for (int j = 0; j < 8; j++) {
            int col = colBase + tx * 4 + (j & 3) + (j >> 2) * 64;
            double t = 2.0 * (double)acc[i][j];       // fl32 doubling is exact
            double d = zz - t;                        // > 0 always (zz ~ 300)
            long long db = __double_as_longlong(d);
            int ebias = (int)((db >> 52) & 0x7ff);
            double cell = __longlong_as_double((long long)(ebias - 23) << 52);
            double r = cell * rint(t / cell);         // exact
            float rf = (float)r;
            unsigned u = __float_as_uint(rf);
            u = (u & 0x80000000u) ? ~u : (u | 0x80000000u);
            unsigned long long key =
                ((unsigned long long)(~u) << 32) | (unsigned)col; // max r, min col
            if (key < best) best = key;
        }
#pragma unroll
        for (int o = 8; o; o >>= 1) {
            unsigned long long oth = __shfl_down_sync(0xffffffffu, best, o, 16);
            if (oth < best) best = oth;
        }
        if (tx == 0) atomicMin(&amin[row], best);
    }
}

// ---------------- VQ finalize: gather q, straight-through zq, loss ----------
__global__ void vq_finalize_kernel(const float* __restrict__ Z,
                                   const float* __restrict__ E,
                                   const unsigned long long* __restrict__ amin,
                                   float* __restrict__ zq,
                                   float* __restrict__ loss)
{
    int row  = blockIdx.x * 8 + (threadIdx.x >> 5);
    int lane = threadIdx.x & 31;
    int idx  = (int)(amin[row] & 0xffffffffull);
    const float4* zp = reinterpret_cast<const float4*>(Z) + (size_t)row * (DLAT / 4);
    const float4* ep = reinterpret_cast<const float4*>(E) + (size_t)idx * (DLAT / 4);
    float4* qp = reinterpret_cast<float4*>(zq) + (size_t)row * (DLAT / 4);
    float s = 0.f;
#pragma unroll
    for (int t = 0; t < 2; t++) {
        float4 z = zp[lane + 32 * t], e = ep[lane + 32 * t];
        float dx = e.x - z.x, dy = e.y - z.y, dz = e.z - z.z, dw = e.w - z.w;
        float4 o;                 // zq = z + (q - z), same op order as reference
        o.x = z.x + dx; o.y = z.y + dy; o.z = z.z + dz; o.w = z.w + dw;
        qp[lane + 32 * t] = o;
        s += dx * dx + dy * dy + dz * dz + dw * dw;
    }
#pragma unroll
    for (int o = 16; o; o >>= 1) s += __shfl_down_sync(0xffffffffu, s, o);
    if (lane == 0) loss[row] = s + BETA_F * s;
}

// ---------------- launcher ----------------
extern "C" void kernel_launch(void* const* d_in, const int* in_sizes, int n_in,
                              void* d_out, int out_size)
{
    const float* x_a      = (const float*)d_in[0];
    const float* x_b      = (const float*)d_in[1];
    const float* enc_a_w  = (const float*)d_in[2];
    const float* enc_a_b  = (const float*)d_in[3];
    const float* enc_a_rw = (const float*)d_in[4];
    const float* enc_a_rb = (const float*)d_in[5];
    const float* enc_b_w  = (const float*)d_in[6];
    const float* enc_b_b  = (const float*)d_in[7];
    const float* enc_b_rw = (const float*)d_in[8];
    const float* enc_b_rb = (const float*)d_in[9];
    const float* dec_a_rw = (const float*)d_in[10];
    const float* dec_a_rb = (const float*)d_in[11];
    const float* dec_a_w  = (const float*)d_in[12];
    const float* dec_a_b  = (const float*)d_in[13];
    const float* dec_b_rw = (const float*)d_in[14];
    const float* dec_b_rb = (const float*)d_in[15];
    const float* dec_b_w  = (const float*)d_in[16];
    const float* dec_b_b  = (const float*)d_in[17];
    const float* codebook = (const float*)d_in[18];

    float *ze_a0, *ze_a1, *ze_b0, *ze_b1, *h0, *h1;
    double *zz_a, *zz_b;
    unsigned long long *amin_a, *amin_b;
    cudaGetSymbolAddress((void**)&ze_a0, g_ze_a0);
    cudaGetSymbolAddress((void**)&ze_a1, g_ze_a1);
    cudaGetSymbolAddress((void**)&ze_b0, g_ze_b0);
    cudaGetSymbolAddress((void**)&ze_b1, g_ze_b1);
    cudaGetSymbolAddress((void**)&h0, g_h0);
    cudaGetSymbolAddress((void**)&h1, g_h1);
    cudaGetSymbolAddress((void**)&zz_a, g_zz_a);
    cudaGetSymbolAddress((void**)&zz_b, g_zz_b);
    cudaGetSymbolAddress((void**)&amin_a, g_amin_a);
    cudaGetSymbolAddress((void**)&amin_b, g_amin_b);

    float* out = (float*)d_out;
    const size_t OFF_ZA = 0;
    const size_t OFF_ZB = (size_t)BATCH * DLAT;
    const size_t OFF_LA = 2 * OFF_ZB;
    const size_t OFF_LB = OFF_LA + BATCH;
    const size_t OFF_RA = OFF_LB + BATCH;
    const size_t OFF_RB = OFF_RA + (size_t)BATCH * DINA;
    const size_t OFF_XA = OFF_RB + (size_t)BATCH * DINB;
    const size_t OFF_XB = OFF_XA + (size_t)BATCH * DINA;

    init_amin_kernel<<<(BATCH + 255) / 256, 256>>>();

    dim3 gLat(DLAT / 128, BATCH / 128);         // (2, 64)  [8192, 256]
    dim3 gLat2(DLAT / 128, 2 * BATCH / 128);    // (2, 128) [16384, 256]

    // encoder A
    gemm_kernel<true, false><<<gLat, 256>>>(x_a, enc_a_w, enc_a_b,
        ze_a0, ze_a0, BATCH, DLAT, DINA);
    gemm_kernel<true, true><<<gLat, 256>>>(ze_a0, enc_a_rw, enc_a_rb,
        ze_a1, ze_a1, BATCH, DLAT, DLAT);
    gemm_kernel<true, true><<<gLat, 256>>>(ze_a1, enc_a_rw + DLAT * DLAT, enc_a_rb + DLAT,
        ze_a0, ze_a0, BATCH, DLAT, DLAT);

    // encoder B
    gemm_kernel<true, false><<<gLat, 256>>>(x_b, enc_b_w, enc_b_b,
        ze_b0, ze_b0, BATCH, DLAT, DINB);
    gemm_kernel<true, true><<<gLat, 256>>>(ze_b0, enc_b_rw, enc_b_rb,
        ze_b1, ze_b1, BATCH, DLAT, DLAT);
    gemm_kernel<true, true><<<gLat, 256>>>(ze_b1, enc_b_rw + DLAT * DLAT, enc_b_rb + DLAT,
        ze_b0, ze_b0, BATCH, DLAT, DLAT);

    // row norms (fp64 binade anchor)
    zz_kernel<<<BATCH / 8, 256>>>(ze_a0, zz_a);
    zz_kernel<<<BATCH / 8, 256>>>(ze_b0, zz_b);

    // VQ argmin
    dim3 gVQ(NCODE / 128, BATCH / 128);         // (64, 64)
    vq_argmin_kernel<<<gVQ, 256>>>(ze_a0, codebook, zz_a, amin_a);
    vq_argmin_kernel<<<gVQ, 256>>>(ze_b0, codebook, zz_b, amin_b);

    vq_finalize_kernel<<<BATCH / 8, 256>>>(ze_a0, codebook, amin_a,
                                           out + OFF_ZA, out + OFF_LA);
    vq_finalize_kernel<<<BATCH / 8, 256>>>(ze_b0, codebook, amin_b,
                                           out + OFF_ZB, out + OFF_LB);

    // decoders, batched over [zq_a; zq_b] (contiguous in d_out)
    const float* Zq = out;

    gemm_kernel<true, true><<<gLat2, 256>>>(Zq, dec_a_rw, dec_a_rb,
        h1, h1, 2 * BATCH, DLAT, DLAT);
    gemm_kernel<true, true><<<gLat2, 256>>>(h1, dec_a_rw + DLAT * DLAT, dec_a_rb + DLAT,
        h0, h0, 2 * BATCH, DLAT, DLAT);
    gemm_kernel<false, false><<<dim3(DINA / 128, 2 * BATCH / 128), 256>>>(
        h0, dec_a_w, dec_a_b,
        out + OFF_RA, out + OFF_XA, BATCH, DINA, DLAT);

    gemm_kernel<true, true><<<gLat2, 256>>>(Zq, dec_b_rw, dec_b_rb,
        h1, h1, 2 * BATCH, DLAT, DLAT);
    gemm_kernel<true, true><<<gLat2, 256>>>(h1, dec_b_rw + DLAT * DLAT, dec_b_rb + DLAT,
        h0, h0, 2 * BATCH, DLAT, DLAT);
    gemm_kernel<false, false><<<dim3(DINB / 128, 2 * BATCH / 128), 256>>>(
        h0, dec_b_w, dec_b_b,
        out + OFF_XB, out + OFF_RB, BATCH, DINB, DLAT);
}

// round 6
// speedup vs baseline: 1.7703x; 1.7703x over previous
#include <cuda_runtime.h>
#include <cstdint>

#define BATCH   8192
#define DINA    4096
#define DINB    2048
#define DLAT    256
#define NCODE   8192
#define BETA_F  0.25f

// ---------------- scratch (static __device__ — no allocation) ----------------
__device__ float g_ze_a0[BATCH * DLAT];
__device__ float g_ze_a1[BATCH * DLAT];
__device__ float g_ze_b0[BATCH * DLAT];
__device__ float g_ze_b1[BATCH * DLAT];
__device__ float g_h0[2 * BATCH * DLAT];
__device__ float g_h1[2 * BATCH * DLAT];
__device__ double g_zz_a[BATCH];
__device__ double g_zz_b[BATCH];
__device__ unsigned long long g_amin_a[BATCH];
__device__ unsigned long long g_amin_b[BATCH];

// ---------------- small helpers ----------------
__global__ void init_amin_kernel() {
    int i = blockIdx.x * blockDim.x + threadIdx.x;
    if (i < BATCH) { g_amin_a[i] = ~0ull; g_amin_b[i] = ~0ull; }
}

// ||z_row||^2 in fp64 (binade anchor for the rounding grid)
__global__ void zz_kernel(const float* __restrict__ Z, double* __restrict__ zz) {
    int row  = blockIdx.x * 8 + (threadIdx.x >> 5);
    int lane = threadIdx.x & 31;
    const float4* zp = reinterpret_cast<const float4*>(Z) + (size_t)row * (DLAT / 4);
    double s = 0.0;
#pragma unroll
    for (int t = 0; t < 2; t++) {
        float4 v = zp[lane + 32 * t];
        s += (double)v.x * v.x + (double)v.y * v.y
           + (double)v.z * v.z + (double)v.w * v.w;
    }
#pragma unroll
    for (int o = 16; o; o >>= 1) s += __shfl_down_sync(0xffffffffu, s, o);
    if (lane == 0) zz[row] = s;
}

// ---------------- generic fused GEMM ----------------
// BM in {64,128}, BN=128, BK=8, 256 threads, single-buffered smem with
// register prefetch. Microtile (BM/16)x8. Per-output accumulation is a single
// fp32 FMA chain over ascending k — bit-identical to rounds 4/5 (argmin-safe).
// C = [RESID? A +] [RELU?] (A @ W + bias); rows < rowSplit -> C0 else C1.
template<int BM, bool RELU, bool RESID>
__global__ __launch_bounds__(256, 2)
void gemm_kernel(const float* __restrict__ A, const float* __restrict__ W,
                 const float* __restrict__ bias,
                 float* __restrict__ C0, float* __restrict__ C1,
                 int rowSplit, int N, int K)
{
    constexpr int TM = BM / 16;
    __shared__ float As[8][BM + 4];
    __shared__ float Bs[8][128];
    const int tid = threadIdx.x;
    const int tx = tid & 15, ty = tid >> 4;
    const int rowBase = blockIdx.y * BM;
    const int colBase = blockIdx.x * 128;

    const int ar = tid >> 1, ac4 = (tid & 1) * 4;   // A: BM rows x 2 float4
    const int br = tid >> 5, bc = (tid & 31) * 4;   // B: 8 rows x 32 float4
    const bool aAct = (BM == 128) || (tid < 2 * BM);
    const float* Ap = aAct ? (A + (size_t)(rowBase + ar) * K + ac4) : A;
    const float* Wp = W + (size_t)br * N + colBase + bc;

    float acc[TM][8];
#pragma unroll
    for (int i = 0; i < TM; i++)
#pragma unroll
        for (int j = 0; j < 8; j++) acc[i][j] = 0.f;

    float4 av = *(const float4*)Ap;
    float4 bv = *(const float4*)Wp;
    if (aAct) {
        As[ac4 + 0][ar] = av.x; As[ac4 + 1][ar] = av.y;
        As[ac4 + 2][ar] = av.z; As[ac4 + 3][ar] = av.w;
    }
    *(float4*)&Bs[br][bc] = bv;
    __syncthreads();

    for (int k0 = 8; k0 < K; k0 += 8) {
        if (aAct) av = *(const float4*)(Ap + k0);
        bv = *(const float4*)(Wp + (size_t)k0 * N);
#pragma unroll
        for (int kk = 0; kk < 8; kk++) {
            float a[TM], b[8];
            float4 t;
            t = *(const float4*)&As[kk][ty * 4];
            a[0] = t.x; a[1] = t.y; a[2] = t.z; a[3] = t.w;
            if (TM == 8) {
                t = *(const float4*)&As[kk][ty * 4 + 64];
                a[4] = t.x; a[5] = t.y; a[6] = t.z; a[7] = t.w;
            }
            t = *(const float4*)&Bs[kk][tx * 4];
            b[0] = t.x; b[1] = t.y; b[2] = t.z; b[3] = t.w;
            t = *(const float4*)&Bs[kk][tx * 4 + 64];
            b[4] = t.x; b[5] = t.y; b[6] = t.z; b[7] = t.w;
#pragma unroll
            for (int i = 0; i < TM; i++)
#pragma unroll
                for (int j = 0; j < 8; j++)
                    acc[i][j] = fmaf(a[i], b[j], acc[i][j]);
        }
        __syncthreads();
        if (aAct) {
            As[ac4 + 0][ar] = av.x; As[ac4 + 1][ar] = av.y;
            As[ac4 + 2][ar] = av.z; As[ac4 + 3][ar] = av.w;
        }
        *(float4*)&Bs[br][bc] = bv;
        __syncthreads();
    }
#pragma unroll
    for (int kk = 0; kk < 8; kk++) {
        float a[TM], b[8];
        float4 t;
        t = *(const float4*)&As[kk][ty * 4];
        a[0] = t.x; a[1] = t.y; a[2] = t.z; a[3] = t.w;
        if (TM == 8) {
            t = *(const float4*)&As[kk][ty * 4 + 64];
            a[4] = t.x; a[5] = t.y; a[6] = t.z; a[7] = t.w;
        }
        t = *(const float4*)&Bs[kk][tx * 4];
        b[0] = t.x; b[1] = t.y; b[2] = t.z; b[3] = t.w;
        t = *(const float4*)&Bs[kk][tx * 4 + 64];
        b[4] = t.x; b[5] = t.y; b[6] = t.z; b[7] = t.w;
#pragma unroll
        for (int i = 0; i < TM; i++)
#pragma unroll
            for (int j = 0; j < 8; j++)
                acc[i][j] = fmaf(a[i], b[j], acc[i][j]);
    }

#pragma unroll
    for (int i = 0; i < TM; i++) {
        int row = (TM == 8) ? (rowBase + ty * 4 + (i & 3) + (i >> 2) * 64)
                            : (rowBase + ty * 4 + i);
        float* cr = (row < rowSplit) ? (C0 + (size_t)row * N)
                                     : (C1 + (size_t)(row - rowSplit) * N);
        const float* rr = RESID ? (A + (size_t)row * K) : nullptr;  // K==N here
#pragma unroll
        for (int g = 0; g < 2; g++) {
            int col = colBase + tx * 4 + g * 64;
            float4 bb = *(const float4*)(bias + col);
            float4 v;
            v.x = acc[i][g * 4 + 0] + bb.x;
            v.y = acc[i][g * 4 + 1] + bb.y;
            v.z = acc[i][g * 4 + 2] + bb.z;
            v.w = acc[i][g * 4 + 3] + bb.w;
            if (RELU) {
                v.x = fmaxf(v.x, 0.f); v.y = fmaxf(v.y, 0.f);
                v.z = fmaxf(v.z, 0.f); v.w = fmaxf(v.w, 0.f);
            }
            if (RESID) {
                float4 rv = *(const float4*)(rr + col);
                v.x += rv.x; v.y += rv.y; v.z += rv.z; v.w += rv.w;
            }
            *(float4*)(cr + col) = v;
        }
    }
}

// ---------------- VQ: fp32-sequential GEMM + rounding-faithful argmin --------
// Identical epilogue math to rounds 4/5 (proven): winner = first k maximizing
// r_k = cell * rint(t_k / cell), cell = ulp-grid of d = zz - t at d's binade.
// Engine: 128x128x8 single-buffered, register-prefetch, 8x8 microtile.
__global__ __launch_bounds__(256, 2)
void vq_argmin_kernel(const float* __restrict__ Z, const float* __restrict__ E,
                      const double* __restrict__ ZZ,
                      unsigned long long* __restrict__ amin)
{
    __shared__ float As[8][132];
    __shared__ float Bs[8][132];
    const int tid = threadIdx.x;
    const int tx = tid & 15, ty = tid >> 4;
    const int rowBase = blockIdx.y * 128;
    const int colBase = blockIdx.x * 128;

    const int ar = tid >> 1, ac4 = (tid & 1) * 4;
    const float* Zp = Z + (size_t)(rowBase + ar) * DLAT + ac4;
    const float* Ep = E + (size_t)(colBase + ar) * DLAT + ac4;  // NT: E rows = N

    float acc[8][8];
#pragma unroll
    for (int i = 0; i < 8; i++)
#pragma unroll
        for (int j = 0; j < 8; j++) acc[i][j] = 0.f;

    float4 av = *(const float4*)Zp;
    float4 ev = *(const float4*)Ep;
    As[ac4 + 0][ar] = av.x; As[ac4 + 1][ar] = av.y;
    As[ac4 + 2][ar] = av.z; As[ac4 + 3][ar] = av.w;
    Bs[ac4 + 0][ar] = ev.x; Bs[ac4 + 1][ar] = ev.y;
    Bs[ac4 + 2][ar] = ev.z; Bs[ac4 + 3][ar] = ev.w;
    __syncthreads();

    for (int k0 = 8; k0 < DLAT; k0 += 8) {
        av = *(const float4*)(Zp + k0);
        ev = *(const float4*)(Ep + k0);
#pragma unroll
        for (int kk = 0; kk < 8; kk++) {
            float a[8], b[8];
            float4 t;
            t = *(const float4*)&As[kk][ty * 4];      a[0]=t.x; a[1]=t.y; a[2]=t.z; a[3]=t.w;
            t = *(const float4*)&As[kk][ty * 4 + 64]; a[4]=t.x; a[5]=t.y; a[6]=t.z; a[7]=t.w;
            t = *(const float4*)&Bs[kk][tx * 4];      b[0]=t.x; b[1]=t.y; b[2]=t.z; b[3]=t.w;
            t = *(const float4*)&Bs[kk][tx * 4 + 64]; b[4]=t.x; b[5]=t.y; b[6]=t.z; b[7]=t.w;
#pragma unroll
            for (int i = 0; i < 8; i++)
#pragma unroll
                for (int j = 0; j < 8; j++)
                    acc[i][j] = fmaf(a[i], b[j], acc[i][j]);
        }
        __syncthreads();
        As[ac4 + 0][ar] = av.x; As[ac4 + 1][ar] = av.y;
        As[ac4 + 2][ar] = av.z; As[ac4 + 3][ar] = av.w;
        Bs[ac4 + 0][ar] = ev.x; Bs[ac4 + 1][ar] = ev.y;
        Bs[ac4 + 2][ar] = ev.z; Bs[ac4 + 3][ar] = ev.w;
        __syncthreads();
    }
#pragma unroll
    for (int kk = 0; kk < 8; kk++) {
        float a[8], b[8];
        float4 t;
        t = *(const float4*)&As[kk][ty * 4];      a[0]=t.x; a[1]=t.y; a[2]=t.z; a[3]=t.w;
        t = *(const float4*)&As[kk][ty * 4 + 64]; a[4]=t.x; a[5]=t.y; a[6]=t.z; a[7]=t.w;
        t = *(const float4*)&Bs[kk][tx * 4];      b[0]=t.x; b[1]=t.y; b[2]=t.z; b[3]=t.w;
        t = *(const float4*)&Bs[kk][tx * 4 + 64]; b[4]=t.x; b[5]=t.y; b[6]=t.z; b[7]=t.w;
#pragma unroll
        for (int i = 0; i < 8; i++)
#pragma unroll
            for (int j = 0; j < 8; j++)
                acc[i][j] = fmaf(a[i], b[j], acc[i][j]);
    }

#pragma unroll
    for (int i = 0; i < 8; i++) {
        int row = rowBase + ty * 4 + (i & 3) + (i >> 2) * 64;
        double zz = ZZ[row];
        unsigned long long best = ~0ull;
#pragma unroll
        for (int j = 0; j < 8; j++) {
            int col = colBase + tx * 4 + (j & 3) + (j >> 2) * 64;
            double t = 2.0 * (double)acc[i][j];       // fl32 doubling is exact
            double d = zz - t;                        // > 0 always (zz ~ 300)
            long long db = __double_as_longlong(d);
            int ebias = (int)((db >> 52) & 0x7ff);
            double cell = __longlong_as_double((long long)(ebias - 23) << 52);
            double r = cell * rint(t / cell);         // exact
            float rf = (float)r;
            unsigned u = __float_as_uint(rf);
            u = (u & 0x80000000u) ? ~u : (u | 0x80000000u);
            unsigned long long key =
                ((unsigned long long)(~u) << 32) | (unsigned)col; // max r, min col
            if (key < best) best = key;
        }
#pragma unroll
        for (int o = 8; o; o >>= 1) {
            unsigned long long oth = __shfl_down_sync(0xffffffffu, best, o, 16);
            if (oth < best) best = oth;
        }
        if (tx == 0) atomicMin(&amin[row], best);
    }
}

// ---------------- VQ finalize: gather q, straight-through zq, loss ----------
__global__ void vq_finalize_kernel(const float* __restrict__ Z,
                                   const float* __restrict__ E,
                                   const unsigned long long* __restrict__ amin,
                                   float* __restrict__ zq,
                                   float* __restrict__ loss)
{
    int row  = blockIdx.x * 8 + (threadIdx.x >> 5);
    int lane = threadIdx.x & 31;
    int idx  = (int)(amin[row] & 0xffffffffull);
    const float4* zp = reinterpret_cast<const float4*>(Z) + (size_t)row * (DLAT / 4);
    const float4* ep = reinterpret_cast<const float4*>(E) + (size_t)idx * (DLAT / 4);
    float4* qp = reinterpret_cast<float4*>(zq) + (size_t)row * (DLAT / 4);
    float s = 0.f;
#pragma unroll
    for (int t = 0; t < 2; t++) {
        float4 z = zp[lane + 32 * t], e = ep[lane + 32 * t];
        float dx = e.x - z.x, dy = e.y - z.y, dz = e.z - z.z, dw = e.w - z.w;
        float4 o;                 // zq = z + (q - z), same op order as reference
        o.x = z.x + dx; o.y = z.y + dy; o.z = z.z + dz; o.w = z.w + dw;
        qp[lane + 32 * t] = o;
        s += dx * dx + dy * dy + dz * dz + dw * dw;
    }
#pragma unroll
    for (int o = 16; o; o >>= 1) s += __shfl_down_sync(0xffffffffu, s, o);
    if (lane == 0) loss[row] = s + BETA_F * s;
}

// ---------------- launcher ----------------
extern "C" void kernel_launch(void* const* d_in, const int* in_sizes, int n_in,
                              void* d_out, int out_size)
{
    const float* x_a      = (const float*)d_in[0];
    const float* x_b      = (const float*)d_in[1];
    const float* enc_a_w  = (const float*)d_in[2];
    const float* enc_a_b  = (const float*)d_in[3];
    const float* enc_a_rw = (const float*)d_in[4];
    const float* enc_a_rb = (const float*)d_in[5];
    const float* enc_b_w  = (const float*)d_in[6];
    const float* enc_b_b  = (const float*)d_in[7];
    const float* enc_b_rw = (const float*)d_in[8];
    const float* enc_b_rb = (const float*)d_in[9];
    const float* dec_a_rw = (const float*)d_in[10];
    const float* dec_a_rb = (const float*)d_in[11];
    const float* dec_a_w  = (const float*)d_in[12];
    const float* dec_a_b  = (const float*)d_in[13];
    const float* dec_b_rw = (const float*)d_in[14];
    const float* dec_b_rb = (const float*)d_in[15];
    const float* dec_b_w  = (const float*)d_in[16];
    const float* dec_b_b  = (const float*)d_in[17];
    const float* codebook = (const float*)d_in[18];

    float *ze_a0, *ze_a1, *ze_b0, *ze_b1, *h0, *h1;
    double *zz_a, *zz_b;
    unsigned long long *amin_a, *amin_b;
    cudaGetSymbolAddress((void**)&ze_a0, g_ze_a0);
    cudaGetSymbolAddress((void**)&ze_a1, g_ze_a1);
    cudaGetSymbolAddress((void**)&ze_b0, g_ze_b0);
    cudaGetSymbolAddress((void**)&ze_b1, g_ze_b1);
    cudaGetSymbolAddress((void**)&h0, g_h0);
    cudaGetSymbolAddress((void**)&h1, g_h1);
    cudaGetSymbolAddress((void**)&zz_a, g_zz_a);
    cudaGetSymbolAddress((void**)&zz_b, g_zz_b);
    cudaGetSymbolAddress((void**)&amin_a, g_amin_a);
    cudaGetSymbolAddress((void**)&amin_b, g_amin_b);

    float* out = (float*)d_out;
    const size_t OFF_ZA = 0;
    const size_t OFF_ZB = (size_t)BATCH * DLAT;
    const size_t OFF_LA = 2 * OFF_ZB;
    const size_t OFF_LB = OFF_LA + BATCH;
    const size_t OFF_RA = OFF_LB + BATCH;
    const size_t OFF_RB = OFF_RA + (size_t)BATCH * DINA;
    const size_t OFF_XA = OFF_RB + (size_t)BATCH * DINB;
    const size_t OFF_XB = OFF_XA + (size_t)BATCH * DINA;

    init_amin_kernel<<<(BATCH + 255) / 256, 256>>>();

    dim3 gLat(DLAT / 128, BATCH / 64);          // (2, 128)  latent [8192, 256]
    dim3 gLat2(DLAT / 128, 2 * BATCH / 64);     // (2, 256)  latent [16384, 256]

    // encoder A (BM=64 latent path: 256 CTAs, high occupancy)
    gemm_kernel<64, true, false><<<gLat, 256>>>(x_a, enc_a_w, enc_a_b,
        ze_a0, ze_a0, BATCH, DLAT, DINA);
    gemm_kernel<64, true, true><<<gLat, 256>>>(ze_a0, enc_a_rw, enc_a_rb,
        ze_a1, ze_a1, BATCH, DLAT, DLAT);
    gemm_kernel<64, true, true><<<gLat, 256>>>(ze_a1, enc_a_rw + DLAT * DLAT, enc_a_rb + DLAT,
        ze_a0, ze_a0, BATCH, DLAT, DLAT);

    // encoder B
    gemm_kernel<64, true, false><<<gLat, 256>>>(x_b, enc_b_w, enc_b_b,
        ze_b0, ze_b0, BATCH, DLAT, DINB);
    gemm_kernel<64, true, true><<<gLat, 256>>>(ze_b0, enc_b_rw, enc_b_rb,
        ze_b1, ze_b1, BATCH, DLAT, DLAT);
    gemm_kernel<64, true, true><<<gLat, 256>>>(ze_b1, enc_b_rw + DLAT * DLAT, enc_b_rb + DLAT,
        ze_b0, ze_b0, BATCH, DLAT, DLAT);

    // row norms (fp64 binade anchor)
    zz_kernel<<<BATCH / 8, 256>>>(ze_a0, zz_a);
    zz_kernel<<<BATCH / 8, 256>>>(ze_b0, zz_b);

    // VQ argmin
    dim3 gVQ(NCODE / 128, BATCH / 128);         // (64, 64)
    vq_argmin_kernel<<<gVQ, 256>>>(ze_a0, codebook, zz_a, amin_a);
    vq_argmin_kernel<<<gVQ, 256>>>(ze_b0, codebook, zz_b, amin_b);

    vq_finalize_kernel<<<BATCH / 8, 256>>>(ze_a0, codebook, amin_a,
                                           out + OFF_ZA, out + OFF_LA);
    vq_finalize_kernel<<<BATCH / 8, 256>>>(ze_b0, codebook, amin_b,
                                           out + OFF_ZB, out + OFF_LB);

    // decoders, batched over [zq_a; zq_b] (contiguous in d_out)
    const float* Zq = out;

    gemm_kernel<64, true, true><<<gLat2, 256>>>(Zq, dec_a_rw, dec_a_rb,
        h1, h1, 2 * BATCH, DLAT, DLAT);
    gemm_kernel<64, true, true><<<gLat2, 256>>>(h1, dec_a_rw + DLAT * DLAT, dec_a_rb + DLAT,
        h0, h0, 2 * BATCH, DLAT, DLAT);
    gemm_kernel<128, false, false><<<dim3(DINA / 128, 2 * BATCH / 128), 256>>>(
        h0, dec_a_w, dec_a_b,
        out + OFF_RA, out + OFF_XA, BATCH, DINA, DLAT);

    gemm_kernel<64, true, true><<<gLat2, 256>>>(Zq, dec_b_rw, dec_b_rb,
        h1, h1, 2 * BATCH, DLAT, DLAT);
    gemm_kernel<64, true, true><<<gLat2, 256>>>(h1, dec_b_rw + DLAT * DLAT, dec_b_rb + DLAT,
        h0, h0, 2 * BATCH, DLAT, DLAT);
    gemm_kernel<128, false, false><<<dim3(DINB / 128, 2 * BATCH / 128), 256>>>(
        h0, dec_b_w, dec_b_b,
        out + OFF_XB, out + OFF_RB, BATCH, DINB, DLAT);
}

// round 8
// speedup vs baseline: 1.8319x; 1.0348x over previous
#include <cuda_runtime.h>
#include <cuda_bf16.h>
#include <cstdint>

#define BATCH   8192
#define DINA    4096
#define DINB    2048
#define DLAT    256
#define NCODE   8192
#define BETA_F  0.25f

// ---------------- scratch (static __device__ — no allocation) ----------------
__device__ float g_ze_a0[BATCH * DLAT];
__device__ float g_ze_a1[BATCH * DLAT];
__device__ float g_ze_b0[BATCH * DLAT];
__device__ float g_ze_b1[BATCH * DLAT];
__device__ float g_h0[2 * BATCH * DLAT];
__device__ float g_h1[2 * BATCH * DLAT];
__device__ double g_zz_a[BATCH];
__device__ double g_zz_b[BATCH];
__device__ unsigned long long g_amin_a[BATCH];
__device__ unsigned long long g_amin_b[BATCH];
// bf16 split operands for tensor-core decoder finals
__device__ __nv_bfloat16 g_ah[2 * BATCH * DLAT];
__device__ __nv_bfloat16 g_al[2 * BATCH * DLAT];
__device__ __nv_bfloat16 g_wth_a[DINA * DLAT];
__device__ __nv_bfloat16 g_wtl_a[DINA * DLAT];
__device__ __nv_bfloat16 g_wth_b[DINB * DLAT];
__device__ __nv_bfloat16 g_wtl_b[DINB * DLAT];

// ---------------- small helpers ----------------
__global__ void init_amin_kernel() {
    int i = blockIdx.x * blockDim.x + threadIdx.x;
    if (i < BATCH) { g_amin_a[i] = ~0ull; g_amin_b[i] = ~0ull; }
}

// ||z_row||^2 in fp64 (binade anchor for the rounding grid)
__global__ void zz_kernel(const float* __restrict__ Z, double* __restrict__ zz) {
    int row  = blockIdx.x * 8 + (threadIdx.x >> 5);
    int lane = threadIdx.x & 31;
    const float4* zp = reinterpret_cast<const float4*>(Z) + (size_t)row * (DLAT / 4);
    double s = 0.0;
#pragma unroll
    for (int t = 0; t < 2; t++) {
        float4 v = zp[lane + 32 * t];
        s += (double)v.x * v.x + (double)v.y * v.y
           + (double)v.z * v.z + (double)v.w * v.w;
    }
#pragma unroll
    for (int o = 16; o; o >>= 1) s += __shfl_down_sync(0xffffffffu, s, o);
    if (lane == 0) zz[row] = s;
}

// ---------------- generic fused GEMM (SIMT fp32, exact chain) ----------------
template<int BM, bool RELU, bool RESID>
__global__ __launch_bounds__(256, 2)
void gemm_kernel(const float* __restrict__ A, const float* __restrict__ W,
                 const float* __restrict__ bias,
                 float* __restrict__ C0, float* __restrict__ C1,
                 int rowSplit, int N, int K)
{
    constexpr int TM = BM / 16;
    __shared__ float As[8][BM + 4];
    __shared__ float Bs[8][128];
    const int tid = threadIdx.x;
    const int tx = tid & 15, ty = tid >> 4;
    const int rowBase = blockIdx.y * BM;
    const int colBase = blockIdx.x * 128;

    const int ar = tid >> 1, ac4 = (tid & 1) * 4;
    const int br = tid >> 5, bc = (tid & 31) * 4;
    const bool aAct = (BM == 128) || (tid < 2 * BM);
    const float* Ap = aAct ? (A + (size_t)(rowBase + ar) * K + ac4) : A;
    const float* Wp = W + (size_t)br * N + colBase + bc;

    float acc[TM][8];
#pragma unroll
    for (int i = 0; i < TM; i++)
#pragma unroll
        for (int j = 0; j < 8; j++) acc[i][j] = 0.f;

    float4 av = *(const float4*)Ap;
    float4 bv = *(const float4*)Wp;
    if (aAct) {
        As[ac4 + 0][ar] = av.x; As[ac4 + 1][ar] = av.y;
        As[ac4 + 2][ar] = av.z; As[ac4 + 3][ar] = av.w;
    }
    *(float4*)&Bs[br][bc] = bv;
    __syncthreads();

    for (int k0 = 8; k0 < K; k0 += 8) {
        if (aAct) av = *(const float4*)(Ap + k0);
        bv = *(const float4*)(Wp + (size_t)k0 * N);
#pragma unroll
        for (int kk = 0; kk < 8; kk++) {
            float a[TM], b[8];
            float4 t;
            t = *(const float4*)&As[kk][ty * 4];
            a[0] = t.x; a[1] = t.y; a[2] = t.z; a[3] = t.w;
            if (TM == 8) {
                t = *(const float4*)&As[kk][ty * 4 + 64];
                a[4] = t.x; a[5] = t.y; a[6] = t.z; a[7] = t.w;
            }
            t = *(const float4*)&Bs[kk][tx * 4];
            b[0] = t.x; b[1] = t.y; b[2] = t.z; b[3] = t.w;
            t = *(const float4*)&Bs[kk][tx * 4 + 64];
            b[4] = t.x; b[5] = t.y; b[6] = t.z; b[7] = t.w;
#pragma unroll
            for (int i = 0; i < TM; i++)
#pragma unroll
                for (int j = 0; j < 8; j++)
                    acc[i][j] = fmaf(a[i], b[j], acc[i][j]);
        }
        __syncthreads();
        if (aAct) {
            As[ac4 + 0][ar] = av.x; As[ac4 + 1][ar] = av.y;
            As[ac4 + 2][ar] = av.z; As[ac4 + 3][ar] = av.w;
        }
        *(float4*)&Bs[br][bc] = bv;
        __syncthreads();
    }
#pragma unroll
    for (int kk = 0; kk < 8; kk++) {
        float a[TM], b[8];
        float4 t;
        t = *(const float4*)&As[kk][ty * 4];
        a[0] = t.x; a[1] = t.y; a[2] = t.z; a[3] = t.w;
        if (TM == 8) {
            t = *(const float4*)&As[kk][ty * 4 + 64];
            a[4] = t.x; a[5] = t.y; a[6] = t.z; a[7] = t.w;
        }
        t = *(const float4*)&Bs[kk][tx * 4];
        b[0] = t.x; b[1] = t.y; b[2] = t.z; b[3] = t.w;
        t = *(const float4*)&Bs[kk][tx * 4 + 64];
        b[4] = t.x; b[5] = t.y; b[6] = t.z; b[7] = t.w;
#pragma unroll
        for (int i = 0; i < TM; i++)
#pragma unroll
            for (int j = 0; j < 8; j++)
                acc[i][j] = fmaf(a[i], b[j], acc[i][j]);
    }

#pragma unroll
    for (int i = 0; i < TM; i++) {
        int row = (TM == 8) ? (rowBase + ty * 4 + (i & 3) + (i >> 2) * 64)
                            : (rowBase + ty * 4 + i);
        float* cr = (row < rowSplit) ? (C0 + (size_t)row * N)
                                     : (C1 + (size_t)(row - rowSplit) * N);
        const float* rr = RESID ? (A + (size_t)row * K) : nullptr;
#pragma unroll
        for (int g = 0; g < 2; g++) {
            int col = colBase + tx * 4 + g * 64;
            float4 bb = *(const float4*)(bias + col);
            float4 v;
            v.x = acc[i][g * 4 + 0] + bb.x;
            v.y = acc[i][g * 4 + 1] + bb.y;
            v.z = acc[i][g * 4 + 2] + bb.z;
            v.w = acc[i][g * 4 + 3] + bb.w;
            if (RELU) {
                v.x = fmaxf(v.x, 0.f); v.y = fmaxf(v.y, 0.f);
                v.z = fmaxf(v.z, 0.f); v.w = fmaxf(v.w, 0.f);
            }
            if (RESID) {
                float4 rv = *(const float4*)(rr + col);
                v.x += rv.x; v.y += rv.y; v.z += rv.z; v.w += rv.w;
            }
            *(float4*)(cr + col) = v;
        }
    }
}

// ---------------- VQ: fp32-sequential GEMM + rounding-faithful argmin --------
__global__ __launch_bounds__(256, 2)
void vq_argmin_kernel(const float* __restrict__ Z, const float* __restrict__ E,
                      const double* __restrict__ ZZ,
                      unsigned long long* __restrict__ amin)
{
    __shared__ float As[8][132];
    __shared__ float Bs[8][132];
    const int tid = threadIdx.x;
    const int tx = tid & 15, ty = tid >> 4;
    const int rowBase = blockIdx.y * 128;
    const int colBase = blockIdx.x * 128;

    const int ar = tid >> 1, ac4 = (tid & 1) * 4;
    const float* Zp = Z + (size_t)(rowBase + ar) * DLAT + ac4;
    const float* Ep = E + (size_t)(colBase + ar) * DLAT + ac4;

    float acc[8][8];
#pragma unroll
    for (int i = 0; i < 8; i++)
#pragma unroll
        for (int j = 0; j < 8; j++) acc[i][j] = 0.f;

    float4 av = *(const float4*)Zp;
    float4 ev = *(const float4*)Ep;
    As[ac4 + 0][ar] = av.x; As[ac4 + 1][ar] = av.y;
    As[ac4 + 2][ar] = av.z; As[ac4 + 3][ar] = av.w;
    Bs[ac4 + 0][ar] = ev.x; Bs[ac4 + 1][ar] = ev.y;
    Bs[ac4 + 2][ar] = ev.z; Bs[ac4 + 3][ar] = ev.w;
    __syncthreads();

    for (int k0 = 8; k0 < DLAT; k0 += 8) {
        av = *(const float4*)(Zp + k0);
        ev = *(const float4*)(Ep + k0);
#pragma unroll
        for (int kk = 0; kk < 8; kk++) {
            float a[8], b[8];
            float4 t;
            t = *(const float4*)&As[kk][ty * 4];      a[0]=t.x; a[1]=t.y; a[2]=t.z; a[3]=t.w;
            t = *(const float4*)&As[kk][ty * 4 + 64]; a[4]=t.x; a[5]=t.y; a[6]=t.z; a[7]=t.w;
            t = *(const float4*)&Bs[kk][tx * 4];      b[0]=t.x; b[1]=t.y; b[2]=t.z; b[3]=t.w;
            t = *(const float4*)&Bs[kk][tx * 4 + 64]; b[4]=t.x; b[5]=t.y; b[6]=t.z; b[7]=t.w;
#pragma unroll
            for (int i = 0; i < 8; i++)
#pragma unroll
                for (int j = 0; j < 8; j++)
                    acc[i][j] = fmaf(a[i], b[j], acc[i][j]);
        }
        __syncthreads();
        As[ac4 + 0][ar] = av.x; As[ac4 + 1][ar] = av.y;
        As[ac4 + 2][ar] = av.z; As[ac4 + 3][ar] = av.w;
        Bs[ac4 + 0][ar] = ev.x; Bs[ac4 + 1][ar] = ev.y;
        Bs[ac4 + 2][ar] = ev.z; Bs[ac4 + 3][ar] = ev.w;
        __syncthreads();
    }
#pragma unroll
    for (int kk = 0; kk < 8; kk++) {
        float a[8], b[8];
        float4 t;
        t = *(const float4*)&As[kk][ty * 4];      a[0]=t.x; a[1]=t.y; a[2]=t.z; a[3]=t.w;
        t = *(const float4*)&As[kk][ty * 4 + 64]; a[4]=t.x; a[5]=t.y; a[6]=t.z; a[7]=t.w;
        t = *(const float4*)&Bs[kk][tx * 4];      b[0]=t.x; b[1]=t.y; b[2]=t.z; b[3]=t.w;
        t = *(const float4*)&Bs[kk][tx * 4 + 64]; b[4]=t.x; b[5]=t.y; b[6]=t.z; b[7]=t.w;
#pragma unroll
        for (int i = 0; i < 8; i++)
#pragma unroll
            for (int j = 0; j < 8; j++)
                acc[i][j] = fmaf(a[i], b[j], acc[i][j]);
    }

#pragma unroll
    for (int i = 0; i < 8; i++) {
        int row = rowBase + ty * 4 + (i & 3) + (i >> 2) * 64;
        double zz = ZZ[row];
        unsigned long long best = ~0ull;
#pragma unroll
        for (int j = 0; j < 8; j++) {
            int col = colBase + tx * 4 + (j & 3) + (j >> 2) * 64;
            double t = 2.0 * (double)acc[i][j];
            double d = zz - t;
            long long db = __double_as_longlong(d);
            int ebias = (int)((db >> 52) & 0x7ff);
            double cell = __longlong_as_double((long long)(ebias - 23) << 52);
            double r = cell * rint(t / cell);
            float rf = (float)r;
            unsigned u = __float_as_uint(rf);
            u = (u & 0x80000000u) ? ~u : (u | 0x80000000u);
            unsigned long long key =
                ((unsigned long long)(~u) << 32) | (unsigned)col;
            if (key < best) best = key;
        }
#pragma unroll
        for (int o = 8; o; o >>= 1) {
            unsigned long long oth = __shfl_down_sync(0xffffffffu, best, o, 16);
            if (oth < best) best = oth;
        }
        if (tx == 0) atomicMin(&amin[row], best);
    }
}

// ---------------- VQ finalize ----------------
__global__ void vq_finalize_kernel(const float* __restrict__ Z,
                                   const float* __restrict__ E,
                                   const unsigned long long* __restrict__ amin,
                                   float* __restrict__ zq,
                                   float* __restrict__ loss)
{
    int row  = blockIdx.x * 8 + (threadIdx.x >> 5);
    int lane = threadIdx.x & 31;
    int idx  = (int)(amin[row] & 0xffffffffull);
    const float4* zp = reinterpret_cast<const float4*>(Z) + (size_t)row * (DLAT / 4);
    const float4* ep = reinterpret_cast<const float4*>(E) + (size_t)idx * (DLAT / 4);
    float4* qp = reinterpret_cast<float4*>(zq) + (size_t)row * (DLAT / 4);
    float s = 0.f;
#pragma unroll
    for (int t = 0; t < 2; t++) {
        float4 z = zp[lane + 32 * t], e = ep[lane + 32 * t];
        float dx = e.x - z.x, dy = e.y - z.y, dz = e.z - z.z, dw = e.w - z.w;
        float4 o;
        o.x = z.x + dx; o.y = z.y + dy; o.z = z.z + dz; o.w = z.w + dw;
        qp[lane + 32 * t] = o;
        s += dx * dx + dy * dy + dz * dz + dw * dw;
    }
#pragma unroll
    for (int o = 16; o; o >>= 1) s += __shfl_down_sync(0xffffffffu, s, o);
    if (lane == 0) loss[row] = s + BETA_F * s;
}

// =================== tensor-core decoder finals (bf16 3-term, mma.sync) =====

// bf16 hi/lo split of fp32 activations (vectorized float4)
__global__ void split_kernel(const float* __restrict__ x,
                             __nv_bfloat16* __restrict__ hi,
                             __nv_bfloat16* __restrict__ lo, int n4)
{
    int i = blockIdx.x * blockDim.x + threadIdx.x;
    if (i >= n4) return;
    float4 v = ((const float4*)x)[i];
    __nv_bfloat16 hx = __float2bfloat16(v.x), hy = __float2bfloat16(v.y);
    __nv_bfloat16 hz = __float2bfloat16(v.z), hw = __float2bfloat16(v.w);
    __nv_bfloat162 h01; h01.x = hx; h01.y = hy;
    __nv_bfloat162 h23; h23.x = hz; h23.y = hw;
    __nv_bfloat162 l01, l23;
    l01.x = __float2bfloat16(v.x - __bfloat162float(hx));
    l01.y = __float2bfloat16(v.y - __bfloat162float(hy));
    l23.x = __float2bfloat16(v.z - __bfloat162float(hz));
    l23.y = __float2bfloat16(v.w - __bfloat162float(hw));
    ((__nv_bfloat162*)hi)[i * 2 + 0] = h01;
    ((__nv_bfloat162*)hi)[i * 2 + 1] = h23;
    ((__nv_bfloat162*)lo)[i * 2 + 0] = l01;
    ((__nv_bfloat162*)lo)[i * 2 + 1] = l23;
}

// transpose W [K=256, N] -> Wt [N, 256] with bf16 hi/lo split (write-coalesced)
__global__ void wtsplit_kernel(const float* __restrict__ W,
                               __nv_bfloat16* __restrict__ th,
                               __nv_bfloat16* __restrict__ tl, int N)
{
    int i = blockIdx.x * blockDim.x + threadIdx.x;  // over N*256, k fastest
    int n = i >> 8, k = i & 255;
    float x = W[(size_t)k * N + n];
    __nv_bfloat16 h = __float2bfloat16(x);
    th[i] = h;
    tl[i] = __float2bfloat16(x - __bfloat162float(h));
}

__device__ __forceinline__ uint32_t smem_u32(const void* p) {
    uint32_t a;
    asm("{ .reg .u64 t; cvta.to.shared.u64 t, %1; cvt.u32.u64 %0, t; }"
        : "=r"(a) : "l"(p));
    return a;
}

// C[M,N] = (Ah+Al) @ (Wh+Wl)^T + bias via 3 bf16 HMMA terms, fp32 reg accum.
// BM=BN=128, BK=32, 8 warps (2x4), warp tile 64x32, m16n8k16 mma + ldmatrix.
// smem row stride 40 bf16 (80B) — conflict-free for ldmatrix 8-row groups.
__global__ __launch_bounds__(256, 2)
void mma_final_kernel(const __nv_bfloat16* __restrict__ Ah,
                      const __nv_bfloat16* __restrict__ Al,
                      const __nv_bfloat16* __restrict__ Bh,
                      const __nv_bfloat16* __restrict__ Bl,
                      const float* __restrict__ bias,
                      float* __restrict__ C0, float* __restrict__ C1,
                      int rowSplit, int N)
{
    __shared__ __align__(16) __nv_bfloat16 As[128][40];
    __shared__ __align__(16) __nv_bfloat16 Bs[128][40];
    const int tid = threadIdx.x;
    const int wid = tid >> 5, lane = tid & 31;
    const int wr = wid >> 2, wc = wid & 3;         // 2 x 4 warp grid
    const int rowBase = blockIdx.y * 128;
    const int colBase = blockIdx.x * 128;

    const int lr = tid >> 1;                        // gmem load row 0..127
    const int lc = (tid & 1) * 2;                   // uint4 pair index within row

    const __nv_bfloat16* Asrc[3] = {Ah, Ah, Al};
    const __nv_bfloat16* Bsrc[3] = {Bh, Bl, Bh};

    float acc[4][4][4];
#pragma unroll
    for (int m = 0; m < 4; m++)
#pragma unroll
        for (int n = 0; n < 4; n++)
#pragma unroll
            for (int c = 0; c < 4; c++) acc[m][n][c] = 0.f;

    // ldmatrix source addresses (per-lane, fixed across iters up to offsets)
    const uint32_t aAddr = smem_u32(&As[wr * 64 + (lane & 15)][(lane >> 4) * 8]);
    const uint32_t bAddr = smem_u32(
        &Bs[wc * 32 + (lane & 7) + ((lane >> 4) & 1) * 8][((lane >> 3) & 1) * 8]);

    uint4 ra0, ra1, rb0, rb1;
    {
        const uint4* ga = (const uint4*)(Asrc[0] + (size_t)(rowBase + lr) * 256);
        ra0 = ga[lc]; ra1 = ga[lc + 1];
        const uint4* gb = (const uint4*)(Bsrc[0] + (size_t)(colBase + lr) * 256);
        rb0 = gb[lc]; rb1 = gb[lc + 1];
    }
    *(uint4*)&As[lr][lc * 8] = ra0; *(uint4*)&As[lr][lc * 8 + 8] = ra1;
    *(uint4*)&Bs[lr][lc * 8] = rb0; *(uint4*)&Bs[lr][lc * 8 + 8] = rb1;
    __syncthreads();

    auto compute = [&]() {
#pragma unroll
        for (int ss = 0; ss < 2; ss++) {
            uint32_t af[4][4];
#pragma unroll
            for (int mt = 0; mt < 4; mt++) {
                uint32_t addr = aAddr + mt * 16 * 80 + ss * 32;
                asm volatile(
                    "ldmatrix.sync.aligned.m8n8.x4.shared.b16 {%0,%1,%2,%3}, [%4];"
                    : "=r"(af[mt][0]), "=r"(af[mt][1]),
                      "=r"(af[mt][2]), "=r"(af[mt][3]) : "r"(addr));
            }
            uint32_t bf[2][4];
#pragma unroll
            for (int bp = 0; bp < 2; bp++) {
                uint32_t addr = bAddr + bp * 16 * 80 + ss * 32;
                asm volatile(
                    "ldmatrix.sync.aligned.m8n8.x4.shared.b16 {%0,%1,%2,%3}, [%4];"
                    : "=r"(bf[bp][0]), "=r"(bf[bp][1]),
                      "=r"(bf[bp][2]), "=r"(bf[bp][3]) : "r"(addr));
            }
#pragma unroll
            for (int mt = 0; mt < 4; mt++)
#pragma unroll
                for (int nt = 0; nt < 4; nt++) {
                    uint32_t b0 = bf[nt >> 1][(nt & 1) * 2 + 0];
                    uint32_t b1 = bf[nt >> 1][(nt & 1) * 2 + 1];
                    asm volatile(
                        "mma.sync.aligned.m16n8k16.row.col.f32.bf16.bf16.f32 "
                        "{%0,%1,%2,%3}, {%4,%5,%6,%7}, {%8,%9}, {%0,%1,%2,%3};"
                        : "+f"(acc[mt][nt][0]), "+f"(acc[mt][nt][1]),
                          "+f"(acc[mt][nt][2]), "+f"(acc[mt][nt][3])
                        : "r"(af[mt][0]), "r"(af[mt][1]),
                          "r"(af[mt][2]), "r"(af[mt][3]), "r"(b0), "r"(b1));
                }
        }
    };

    for (int iter = 1; iter < 24; iter++) {
        const int t = iter >> 3, k0 = (iter & 7) << 5;
        const uint4* ga = (const uint4*)(Asrc[t] + (size_t)(rowBase + lr) * 256 + k0);
        ra0 = ga[lc]; ra1 = ga[lc + 1];
        const uint4* gb = (const uint4*)(Bsrc[t] + (size_t)(colBase + lr) * 256 + k0);
        rb0 = gb[lc]; rb1 = gb[lc + 1];
        compute();
        __syncthreads();
        *(uint4*)&As[lr][lc * 8] = ra0; *(uint4*)&As[lr][lc * 8 + 8] = ra1;
        *(uint4*)&Bs[lr][lc * 8] = rb0; *(uint4*)&Bs[lr][lc * 8 + 8] = rb1;
        __syncthreads();
    }
    compute();

    // epilogue: bias add, rowSplit dual-output
#pragma unroll
    for (int mt = 0; mt < 4; mt++) {
        int row0 = rowBase + wr * 64 + mt * 16 + (lane >> 2);
#pragma unroll
        for (int h = 0; h < 2; h++) {
            int row = row0 + h * 8;
            float* cr = (row < rowSplit) ? (C0 + (size_t)row * N)
                                         : (C1 + (size_t)(row - rowSplit) * N);
#pragma unroll
            for (int nt = 0; nt < 4; nt++) {
                int col = colBase + wc * 32 + nt * 8 + (lane & 3) * 2;
                float2 bb = *(const float2*)(bias + col);
                float2 v;
                v.x = acc[mt][nt][h * 2 + 0] + bb.x;
                v.y = acc[mt][nt][h * 2 + 1] + bb.y;
                *(float2*)(cr + col) = v;
            }
        }
    }
}

// ---------------- launcher ----------------
extern "C" void kernel_launch(void* const* d_in, const int* in_sizes, int n_in,
                              void* d_out, int out_size)
{
    const float* x_a      = (const float*)d_in[0];
    const float* x_b      = (const float*)d_in[1];
    const float* enc_a_w  = (const float*)d_in[2];
    const float* enc_a_b  = (const float*)d_in[3];
    const float* enc_a_rw = (const float*)d_in[4];
    const float* enc_a_rb = (const float*)d_in[5];
    const float* enc_b_w  = (const float*)d_in[6];
    const float* enc_b_b  = (const float*)d_in[7];
    const float* enc_b_rw = (const float*)d_in[8];
    const float* enc_b_rb = (const float*)d_in[9];
    const float* dec_a_rw = (const float*)d_in[10];
    const float* dec_a_rb = (const float*)d_in[11];
    const float* dec_a_w  = (const float*)d_in[12];
    const float* dec_a_b  = (const float*)d_in[13];
    const float* dec_b_rw = (const float*)d_in[14];
    const float* dec_b_rb = (const float*)d_in[15];
    const float* dec_b_w  = (const float*)d_in[16];
    const float* dec_b_b  = (const float*)d_in[17];
    const float* codebook = (const float*)d_in[18];

    float *ze_a0, *ze_a1, *ze_b0, *ze_b1, *h0, *h1;
    double *zz_a, *zz_b;
    unsigned long long *amin_a, *amin_b;
    __nv_bfloat16 *ah, *al, *wth_a, *wtl_a, *wth_b, *wtl_b;
    cudaGetSymbolAddress((void**)&ze_a0, g_ze_a0);
    cudaGetSymbolAddress((void**)&ze_a1, g_ze_a1);
    cudaGetSymbolAddress((void**)&ze_b0, g_ze_b0);
    cudaGetSymbolAddress((void**)&ze_b1, g_ze_b1);
    cudaGetSymbolAddress((void**)&h0, g_h0);
    cudaGetSymbolAddress((void**)&h1, g_h1);
    cudaGetSymbolAddress((void**)&zz_a, g_zz_a);
    cudaGetSymbolAddress((void**)&zz_b, g_zz_b);
    cudaGetSymbolAddress((void**)&amin_a, g_amin_a);
    cudaGetSymbolAddress((void**)&amin_b, g_amin_b);
    cudaGetSymbolAddress((void**)&ah, g_ah);
    cudaGetSymbolAddress((void**)&al, g_al);
    cudaGetSymbolAddress((void**)&wth_a, g_wth_a);
    cudaGetSymbolAddress((void**)&wtl_a, g_wtl_a);
    cudaGetSymbolAddress((void**)&wth_b, g_wth_b);
    cudaGetSymbolAddress((void**)&wtl_b, g_wtl_b);

    float* out = (float*)d_out;
    const size_t OFF_ZA = 0;
    const size_t OFF_ZB = (size_t)BATCH * DLAT;
    const size_t OFF_LA = 2 * OFF_ZB;
    const size_t OFF_LB = OFF_LA + BATCH;
    const size_t OFF_RA = OFF_LB + BATCH;
    const size_t OFF_RB = OFF_RA + (size_t)BATCH * DINA;
    const size_t OFF_XA = OFF_RB + (size_t)BATCH * DINB;
    const size_t OFF_XB = OFF_XA + (size_t)BATCH * DINA;

    init_amin_kernel<<<(BATCH + 255) / 256, 256>>>();
    // W transpose + bf16 hi/lo split (inputs only — run up front)
    wtsplit_kernel<<<DINA, 256>>>(dec_a_w, wth_a, wtl_a, DINA);
    wtsplit_kernel<<<DINB, 256>>>(dec_b_w, wth_b, wtl_b, DINB);

    dim3 gLat(DLAT / 128, BATCH / 64);
    dim3 gLat2(DLAT / 128, 2 * BATCH / 64);

    // encoder A (exact fp32 — argmin-critical)
    gemm_kernel<64, true, false><<<gLat, 256>>>(x_a, enc_a_w, enc_a_b,
        ze_a0, ze_a0, BATCH, DLAT, DINA);
    gemm_kernel<64, true, true><<<gLat, 256>>>(ze_a0, enc_a_rw, enc_a_rb,
        ze_a1, ze_a1, BATCH, DLAT, DLAT);
    gemm_kernel<64, true, true><<<gLat, 256>>>(ze_a1, enc_a_rw + DLAT * DLAT, enc_a_rb + DLAT,
        ze_a0, ze_a0, BATCH, DLAT, DLAT);

    // encoder B
    gemm_kernel<64, true, false><<<gLat, 256>>>(x_b, enc_b_w, enc_b_b,
        ze_b0, ze_b0, BATCH, DLAT, DINB);
    gemm_kernel<64, true, true><<<gLat, 256>>>(ze_b0, enc_b_rw, enc_b_rb,
        ze_b1, ze_b1, BATCH, DLAT, DLAT);
    gemm_kernel<64, true, true><<<gLat, 256>>>(ze_b1, enc_b_rw + DLAT * DLAT, enc_b_rb + DLAT,
        ze_b0, ze_b0, BATCH, DLAT, DLAT);

    zz_kernel<<<BATCH / 8, 256>>>(ze_a0, zz_a);
    zz_kernel<<<BATCH / 8, 256>>>(ze_b0, zz_b);

    dim3 gVQ(NCODE / 128, BATCH / 128);
    vq_argmin_kernel<<<gVQ, 256>>>(ze_a0, codebook, zz_a, amin_a);
    vq_argmin_kernel<<<gVQ, 256>>>(ze_b0, codebook, zz_b, amin_b);

    vq_finalize_kernel<<<BATCH / 8, 256>>>(ze_a0, codebook, amin_a,
                                           out + OFF_ZA, out + OFF_LA);
    vq_finalize_kernel<<<BATCH / 8, 256>>>(ze_b0, codebook, amin_b,
                                           out + OFF_ZB, out + OFF_LB);

    const float* Zq = out;
    const int n4 = 2 * BATCH * DLAT / 4;

    // decoder A: res blocks (exact SIMT), then bf16 3-term tensor final
    gemm_kernel<64, true, true><<<gLat2, 256>>>(Zq, dec_a_rw, dec_a_rb,
        h1, h1, 2 * BATCH, DLAT, DLAT);
    gemm_kernel<64, true, true><<<gLat2, 256>>>(h1, dec_a_rw + DLAT * DLAT, dec_a_rb + DLAT,
        h0, h0, 2 * BATCH, DLAT, DLAT);
    split_kernel<<<(n4 + 255) / 256, 256>>>(h0, ah, al, n4);
    mma_final_kernel<<<dim3(DINA / 128, 2 * BATCH / 128), 256>>>(
        ah, al, wth_a, wtl_a, dec_a_b,
        out + OFF_RA, out + OFF_XA, BATCH, DINA);

    // decoder B
    gemm_kernel<64, true, true><<<gLat2, 256>>>(Zq, dec_b_rw, dec_b_rb,
        h1, h1, 2 * BATCH, DLAT, DLAT);
    gemm_kernel<64, true, true><<<gLat2, 256>>>(h1, dec_b_rw + DLAT * DLAT, dec_b_rb + DLAT,
        h0, h0, 2 * BATCH, DLAT, DLAT);
    split_kernel<<<(n4 + 255) / 256, 256>>>(h0, ah, al, n4);
    mma_final_kernel<<<dim3(DINB / 128, 2 * BATCH / 128), 256>>>(
        ah, al, wth_b, wtl_b, dec_b_b,
        out + OFF_XB, out + OFF_RB, BATCH, DINB);
}

// round 10
// speedup vs baseline: 1.9964x; 1.0898x over previous
#include <cuda_runtime.h>
#include <cuda_bf16.h>
#include <cstdint>

#define BATCH   8192
#define DINA    4096
#define DINB    2048
#define DLAT    256
#define NCODE   8192
#define BETA_F  0.25f

// ---------------- scratch (static __device__ — no allocation) ----------------
__device__ float g_ze_a0[BATCH * DLAT];
__device__ float g_ze_a1[BATCH * DLAT];
__device__ float g_ze_b0[BATCH * DLAT];
__device__ float g_ze_b1[BATCH * DLAT];
__device__ float g_h0a[2 * BATCH * DLAT];
__device__ float g_h1a[2 * BATCH * DLAT];
__device__ float g_h0b[2 * BATCH * DLAT];
__device__ float g_h1b[2 * BATCH * DLAT];
__device__ double g_zz_a[BATCH];
__device__ double g_zz_b[BATCH];
__device__ unsigned long long g_amin_a[BATCH];
__device__ unsigned long long g_amin_b[BATCH];
// bf16 split operands for tensor-core decoder finals
__device__ __nv_bfloat16 g_ah_a[2 * BATCH * DLAT];
__device__ __nv_bfloat16 g_al_a[2 * BATCH * DLAT];
__device__ __nv_bfloat16 g_ah_b[2 * BATCH * DLAT];
__device__ __nv_bfloat16 g_al_b[2 * BATCH * DLAT];
__device__ __nv_bfloat16 g_wth_a[DINA * DLAT];
__device__ __nv_bfloat16 g_wtl_a[DINA * DLAT];
__device__ __nv_bfloat16 g_wth_b[DINB * DLAT];
__device__ __nv_bfloat16 g_wtl_b[DINB * DLAT];

__device__ __forceinline__ uint32_t smem_u32(const void* p) {
    uint32_t a;
    asm("{ .reg .u64 t; cvta.to.shared.u64 t, %1; cvt.u32.u64 %0, t; }"
        : "=r"(a) : "l"(p));
    return a;
}
__device__ __forceinline__ void cp16(uint32_t s, const void* g) {
    asm volatile("cp.async.cg.shared.global [%0], [%1], 16;" :: "r"(s), "l"(g));
}

// ---------------- small helpers ----------------
__global__ void init_amin_kernel() {
    int i = blockIdx.x * blockDim.x + threadIdx.x;
    if (i < BATCH) { g_amin_a[i] = ~0ull; g_amin_b[i] = ~0ull; }
}

// ||z_row||^2 in fp64 (binade anchor); batched a/b over blockIdx.y
__global__ void zz_kernel(const float* __restrict__ Z0, const float* __restrict__ Z1,
                          double* __restrict__ zz0, double* __restrict__ zz1) {
    const float* Z = blockIdx.y ? Z1 : Z0;
    double* zz = blockIdx.y ? zz1 : zz0;
    int row  = blockIdx.x * 8 + (threadIdx.x >> 5);
    int lane = threadIdx.x & 31;
    const float4* zp = reinterpret_cast<const float4*>(Z) + (size_t)row * (DLAT / 4);
    double s = 0.0;
#pragma unroll
    for (int t = 0; t < 2; t++) {
        float4 v = zp[lane + 32 * t];
        s += (double)v.x * v.x + (double)v.y * v.y
           + (double)v.z * v.z + (double)v.w * v.w;
    }
#pragma unroll
    for (int o = 16; o; o >>= 1) s += __shfl_down_sync(0xffffffffu, s, o);
    if (lane == 0) zz[row] = s;
}

// ---------------- SIMT fused GEMM: cp.async + double-buffer, 1 sync/iter ----
// BM=64, BN=128 (N fixed at 256), BK=8. Exact ascending-k fp32 FMA chain.
struct GArgs { const float* A; const float* W; const float* bias; float* C; int K; };

template<bool RELU, bool RESID>
__global__ __launch_bounds__(256, 3)
void gemm_kernel(GArgs g0, GArgs g1)
{
    const GArgs g = blockIdx.z ? g1 : g0;
    const int K = g.K;
    __shared__ float As[2][8][68];
    __shared__ float Bs[2][8][128];
    const int tid = threadIdx.x;
    const int tx = tid & 15, ty = tid >> 4;
    const int rowBase = blockIdx.y * 64;
    const int colBase = blockIdx.x * 128;

    const int ar = tid >> 1, ac4 = (tid & 1) * 4;   // A: 64 rows x 2 float4
    const bool aAct = tid < 128;
    const float* Ap = aAct ? (g.A + (size_t)(rowBase + ar) * K + ac4) : g.A;
    const int br = tid >> 5, bc = (tid & 31) * 4;   // B: 8 rows x 32 float4
    const float* Wp = g.W + (size_t)br * 256 + colBase + bc;
    const uint32_t bs0 = smem_u32(&Bs[0][br][bc]);
    const uint32_t bs1 = smem_u32(&Bs[1][br][bc]);

    float acc[4][8];
#pragma unroll
    for (int i = 0; i < 4; i++)
#pragma unroll
        for (int j = 0; j < 8; j++) acc[i][j] = 0.f;

    // prologue: stage 0
    float4 av = make_float4(0.f, 0.f, 0.f, 0.f);
    if (aAct) av = *(const float4*)Ap;
    cp16(bs0, Wp);
    asm volatile("cp.async.commit_group;");
    if (aAct) {
        As[0][ac4 + 0][ar] = av.x; As[0][ac4 + 1][ar] = av.y;
        As[0][ac4 + 2][ar] = av.z; As[0][ac4 + 3][ar] = av.w;
    }
    asm volatile("cp.async.wait_group 0;");
    __syncthreads();

    const int nIter = K >> 3;
    int buf = 0;
#pragma unroll 1
    for (int i = 0; i < nIter; i++) {
        const bool more = (i + 1 < nIter);
        if (more) {
            if (aAct) av = *(const float4*)(Ap + (size_t)(i + 1) * 8);
            cp16(buf ? bs0 : bs1, Wp + (size_t)(i + 1) * 8 * 256);
            asm volatile("cp.async.commit_group;");
        }
#pragma unroll
        for (int kk = 0; kk < 8; kk++) {
            float4 a4 = *(const float4*)&As[buf][kk][ty * 4];
            float4 b0 = *(const float4*)&Bs[buf][kk][tx * 4];
            float4 b1 = *(const float4*)&Bs[buf][kk][tx * 4 + 64];
            float a[4] = {a4.x, a4.y, a4.z, a4.w};
            float b[8] = {b0.x, b0.y, b0.z, b0.w, b1.x, b1.y, b1.z, b1.w};
#pragma unroll
            for (int i2 = 0; i2 < 4; i2++)
#pragma unroll
                for (int j = 0; j < 8; j++)
                    acc[i2][j] = fmaf(a[i2], b[j], acc[i2][j]);
        }
        if (more) {
            if (aAct) {
                int nb = buf ^ 1;
                As[nb][ac4 + 0][ar] = av.x; As[nb][ac4 + 1][ar] = av.y;
                As[nb][ac4 + 2][ar] = av.z; As[nb][ac4 + 3][ar] = av.w;
            }
            asm volatile("cp.async.wait_group 0;");
        }
        __syncthreads();
        buf ^= 1;
    }

#pragma unroll
    for (int i2 = 0; i2 < 4; i2++) {
        int row = rowBase + ty * 4 + i2;
        float* cr = g.C + (size_t)row * 256;
        const float* rr = RESID ? (g.A + (size_t)row * 256) : nullptr;  // K==256
#pragma unroll
        for (int gg = 0; gg < 2; gg++) {
            int col = colBase + tx * 4 + gg * 64;
            float4 bb = *(const float4*)(g.bias + col);
            float4 v;
            v.x = acc[i2][gg * 4 + 0] + bb.x;
            v.y = acc[i2][gg * 4 + 1] + bb.y;
            v.z = acc[i2][gg * 4 + 2] + bb.z;
            v.w = acc[i2][gg * 4 + 3] + bb.w;
            if (RELU) {
                v.x = fmaxf(v.x, 0.f); v.y = fmaxf(v.y, 0.f);
                v.z = fmaxf(v.z, 0.f); v.w = fmaxf(v.w, 0.f);
            }
            if (RESID) {
                float4 rv = *(const float4*)(rr + col);
                v.x += rv.x; v.y += rv.y; v.z += rv.z; v.w += rv.w;
            }
            *(float4*)(cr + col) = v;
        }
    }
}

// ---------------- VQ: 128x64 tile, double-buffered, 1 sync/iter -------------
// Exact ascending-k fp32 chain + the proven rounding-grid argmin epilogue.
__global__ __launch_bounds__(256, 3)
void vq_argmin_kernel(const float* __restrict__ Z0, const float* __restrict__ Z1,
                      const float* __restrict__ E,
                      const double* __restrict__ ZZ0, const double* __restrict__ ZZ1,
                      unsigned long long* __restrict__ am0,
                      unsigned long long* __restrict__ am1)
{
    const float* Z = blockIdx.z ? Z1 : Z0;
    const double* ZZ = blockIdx.z ? ZZ1 : ZZ0;
    unsigned long long* amin = blockIdx.z ? am1 : am0;
    __shared__ float As[2][8][132];
    __shared__ float Bs[2][8][68];
    const int tid = threadIdx.x;
    const int tx = tid & 15, ty = tid >> 4;
    const int rowBase = blockIdx.y * 128;
    const int colBase = blockIdx.x * 64;

    const int zr = tid >> 1, zc4 = (tid & 1) * 4;   // Z: 128 rows x 2 float4
    const bool eAct = tid < 128;
    const float* Zp = Z + (size_t)(rowBase + zr) * DLAT + zc4;
    const float* Ep = eAct ? (E + (size_t)(colBase + zr) * DLAT + zc4) : E;

    float acc[8][4];
#pragma unroll
    for (int i = 0; i < 8; i++)
#pragma unroll
        for (int j = 0; j < 4; j++) acc[i][j] = 0.f;

    float4 av = *(const float4*)Zp;
    float4 ev = make_float4(0.f, 0.f, 0.f, 0.f);
    if (eAct) ev = *(const float4*)Ep;
    As[0][zc4 + 0][zr] = av.x; As[0][zc4 + 1][zr] = av.y;
    As[0][zc4 + 2][zr] = av.z; As[0][zc4 + 3][zr] = av.w;
    if (eAct) {
        Bs[0][zc4 + 0][zr] = ev.x; Bs[0][zc4 + 1][zr] = ev.y;
        Bs[0][zc4 + 2][zr] = ev.z; Bs[0][zc4 + 3][zr] = ev.w;
    }
    __syncthreads();

    int buf = 0;
#pragma unroll 1
    for (int i = 0; i < 32; i++) {
        const bool more = (i + 1 < 32);
        if (more) {
            av = *(const float4*)(Zp + (size_t)(i + 1) * 8);
            if (eAct) ev = *(const float4*)(Ep + (size_t)(i + 1) * 8);
        }
#pragma unroll
        for (int kk = 0; kk < 8; kk++) {
            float4 a0 = *(const float4*)&As[buf][kk][ty * 4];
            float4 a1 = *(const float4*)&As[buf][kk][ty * 4 + 64];
            float4 b4 = *(const float4*)&Bs[buf][kk][tx * 4];
            float a[8] = {a0.x, a0.y, a0.z, a0.w, a1.x, a1.y, a1.z, a1.w};
            float b[4] = {b4.x, b4.y, b4.z, b4.w};
#pragma unroll
            for (int i2 = 0; i2 < 8; i2++)
#pragma unroll
                for (int j = 0; j < 4; j++)
                    acc[i2][j] = fmaf(a[i2], b[j], acc[i2][j]);
        }
        if (more) {
            int nb = buf ^ 1;
            As[nb][zc4 + 0][zr] = av.x; As[nb][zc4 + 1][zr] = av.y;
            As[nb][zc4 + 2][zr] = av.z; As[nb][zc4 + 3][zr] = av.w;
            if (eAct) {
                Bs[nb][zc4 + 0][zr] = ev.x; Bs[nb][zc4 + 1][zr] = ev.y;
                Bs[nb][zc4 + 2][zr] = ev.z; Bs[nb][zc4 + 3][zr] = ev.w;
            }
        }
        __syncthreads();
        buf ^= 1;
    }

#pragma unroll
    for (int i = 0; i < 8; i++) {
        int row = rowBase + ty * 4 + (i & 3) + (i >> 2) * 64;
        double zz = ZZ[row];
        unsigned long long best = ~0ull;
#pragma unroll
        for (int j = 0; j < 4; j++) {
            int col = colBase + tx * 4 + j;
            double t = 2.0 * (double)acc[i][j];       // fl32 doubling is exact
            double d = zz - t;                        // > 0 always (zz ~ 300)
            long long db = __double_as_longlong(d);
            int ebias = (int)((db >> 52) & 0x7ff);
            double cell = __longlong_as_double((long long)(ebias - 23) << 52);
            double r = cell * rint(t / cell);         // exact
            float rf = (float)r;
            unsigned u = __float_as_uint(rf);
            u = (u & 0x80000000u) ? ~u : (u | 0x80000000u);
            unsigned long long key =
                ((unsigned long long)(~u) << 32) | (unsigned)col; // max r, min col
            if (key < best) best = key;
        }
#pragma unroll
        for (int o = 8; o; o >>= 1) {
            unsigned long long oth = __shfl_down_sync(0xffffffffu, best, o, 16);
            if (oth < best) best = oth;
        }
        if (tx == 0) atomicMin(&amin[row], best);
    }
}

// ---------------- VQ finalize (batched a/b over blockIdx.y) -----------------
__global__ void vq_finalize_kernel(const float* __restrict__ Z0, const float* __restrict__ Z1,
                                   const float* __restrict__ E,
                                   const unsigned long long* __restrict__ am0,
                                   const unsigned long long* __restrict__ am1,
                                   float* __restrict__ zq0, float* __restrict__ zq1,
                                   float* __restrict__ ls0, float* __restrict__ ls1)
{
    const float* Z = blockIdx.y ? Z1 : Z0;
    const unsigned long long* amin = blockIdx.y ? am1 : am0;
    float* zq = blockIdx.y ? zq1 : zq0;
    float* loss = blockIdx.y ? ls1 : ls0;
    int row  = blockIdx.x * 8 + (threadIdx.x >> 5);
    int lane = threadIdx.x & 31;
    int idx  = (int)(amin[row] & 0xffffffffull);
    const float4* zp = reinterpret_cast<const float4*>(Z) + (size_t)row * (DLAT / 4);
    const float4* ep = reinterpret_cast<const float4*>(E) + (size_t)idx * (DLAT / 4);
    float4* qp = reinterpret_cast<float4*>(zq) + (size_t)row * (DLAT / 4);
    float s = 0.f;
#pragma unroll
    for (int t = 0; t < 2; t++) {
        float4 z = zp[lane + 32 * t], e = ep[lane + 32 * t];
        float dx = e.x - z.x, dy = e.y - z.y, dz = e.z - z.z, dw = e.w - z.w;
        float4 o;
        o.x = z.x + dx; o.y = z.y + dy; o.z = z.z + dz; o.w = z.w + dw;
        qp[lane + 32 * t] = o;
        s += dx * dx + dy * dy + dz * dz + dw * dw;
    }
#pragma unroll
    for (int o = 16; o; o >>= 1) s += __shfl_down_sync(0xffffffffu, s, o);
    if (lane == 0) loss[row] = s + BETA_F * s;
}

// =================== tensor-core decoder finals (bf16 3-term, mma.sync) =====

// bf16 hi/lo split of fp32 activations; batched over blockIdx.y
__global__ void split_kernel(const float* __restrict__ x0, const float* __restrict__ x1,
                             __nv_bfloat16* __restrict__ h0, __nv_bfloat16* __restrict__ l0,
                             __nv_bfloat16* __restrict__ h1, __nv_bfloat16* __restrict__ l1,
                             int n4)
{
    const float* x = blockIdx.y ? x1 : x0;
    __nv_bfloat16* hi = blockIdx.y ? h1 : h0;
    __nv_bfloat16* lo = blockIdx.y ? l1 : l0;
    int i = blockIdx.x * blockDim.x + threadIdx.x;
    if (i >= n4) return;
    float4 v = ((const float4*)x)[i];
    __nv_bfloat16 hx = __float2bfloat16(v.x), hy = __float2bfloat16(v.y);
    __nv_bfloat16 hz = __float2bfloat16(v.z), hw = __float2bfloat16(v.w);
    __nv_bfloat162 h01; h01.x = hx; h01.y = hy;
    __nv_bfloat162 h23; h23.x = hz; h23.y = hw;
    __nv_bfloat162 l01, l23;
    l01.x = __float2bfloat16(v.x - __bfloat162float(hx));
    l01.y = __float2bfloat16(v.y - __bfloat162float(hy));
    l23.x = __float2bfloat16(v.z - __bfloat162float(hz));
    l23.y = __float2bfloat16(v.w - __bfloat162float(hw));
    ((__nv_bfloat162*)hi)[i * 2 + 0] = h01;
    ((__nv_bfloat162*)hi)[i * 2 + 1] = h23;
    ((__nv_bfloat162*)lo)[i * 2 + 0] = l01;
    ((__nv_bfloat162*)lo)[i * 2 + 1] = l23;
}

// transpose W [K=256, N] -> Wt [N, 256] with bf16 hi/lo split
__global__ void wtsplit_kernel(const float* __restrict__ W,
                               __nv_bfloat16* __restrict__ th,
                               __nv_bfloat16* __restrict__ tl, int N)
{
    int i = blockIdx.x * blockDim.x + threadIdx.x;  // over N*256, k fastest
    int n = i >> 8, k = i & 255;
    float x = W[(size_t)k * N + n];
    __nv_bfloat16 h = __float2bfloat16(x);
    th[i] = h;
    tl[i] = __float2bfloat16(x - __bfloat162float(h));
}

// C[M,N] = (Ah+Al) @ (Wh+Wl)^T + bias via 3 bf16 HMMA terms, fp32 reg accum.
__global__ __launch_bounds__(256, 2)
void mma_final_kernel(const __nv_bfloat16* __restrict__ Ah,
                      const __nv_bfloat16* __restrict__ Al,
                      const __nv_bfloat16* __restrict__ Bh,
                      const __nv_bfloat16* __restrict__ Bl,
                      const float* __restrict__ bias,
                      float* __restrict__ C0, float* __restrict__ C1,
                      int rowSplit, int N)
{
    __shared__ __align__(16) __nv_bfloat16 As[128][40];
    __shared__ __align__(16) __nv_bfloat16 Bs[128][40];
    const int tid = threadIdx.x;
    const int wid = tid >> 5, lane = tid & 31;
    const int wr = wid >> 2, wc = wid & 3;
    const int rowBase = blockIdx.y * 128;
    const int colBase = blockIdx.x * 128;

    const int lr = tid >> 1;
    const int lc = (tid & 1) * 2;

    const __nv_bfloat16* Asrc[3] = {Ah, Ah, Al};
    const __nv_bfloat16* Bsrc[3] = {Bh, Bl, Bh};

    float acc[4][4][4];
#pragma unroll
    for (int m = 0; m < 4; m++)
#pragma unroll
        for (int n = 0; n < 4; n++)
#pragma unroll
            for (int c = 0; c < 4; c++) acc[m][n][c] = 0.f;

    const uint32_t aAddr = smem_u32(&As[wr * 64 + (lane & 15)][(lane >> 4) * 8]);
    const uint32_t bAddr = smem_u32(
        &Bs[wc * 32 + (lane & 7) + ((lane >> 4) & 1) * 8][((lane >> 3) & 1) * 8]);

    uint4 ra0, ra1, rb0, rb1;
    {
        const uint4* ga = (const uint4*)(Asrc[0] + (size_t)(rowBase + lr) * 256);
        ra0 = ga[lc]; ra1 = ga[lc + 1];
        const uint4* gb = (const uint4*)(Bsrc[0] + (size_t)(colBase + lr) * 256);
        rb0 = gb[lc]; rb1 = gb[lc + 1];
    }
    *(uint4*)&As[lr][lc * 8] = ra0; *(uint4*)&As[lr][lc * 8 + 8] = ra1;
    *(uint4*)&Bs[lr][lc * 8] = rb0; *(uint4*)&Bs[lr][lc * 8 + 8] = rb1;
    __syncthreads();

    auto compute = [&]() {
#pragma unroll
        for (int ss = 0; ss < 2; ss++) {
            uint32_t af[4][4];
#pragma unroll
            for (int mt = 0; mt < 4; mt++) {
                uint32_t addr = aAddr + mt * 16 * 80 + ss * 32;
                asm volatile(
                    "ldmatrix.sync.aligned.m8n8.x4.shared.b16 {%0,%1,%2,%3}, [%4];"
                    : "=r"(af[mt][0]), "=r"(af[mt][1]),
                      "=r"(af[mt][2]), "=r"(af[mt][3]) : "r"(addr));
            }
            uint32_t bf[2][4];
#pragma unroll
            for (int bp = 0; bp < 2; bp++) {
                uint32_t addr = bAddr + bp * 16 * 80 + ss * 32;
                asm volatile(
                    "ldmatrix.sync.aligned.m8n8.x4.shared.b16 {%0,%1,%2,%3}, [%4];"
                    : "=r"(bf[bp][0]), "=r"(bf[bp][1]),
                      "=r"(bf[bp][2]), "=r"(bf[bp][3]) : "r"(addr));
            }
#pragma unroll
            for (int mt = 0; mt < 4; mt++)
#pragma unroll
                for (int nt = 0; nt < 4; nt++) {
                    uint32_t b0 = bf[nt >> 1][(nt & 1) * 2 + 0];
                    uint32_t b1 = bf[nt >> 1][(nt & 1) * 2 + 1];
                    asm volatile(
                        "mma.sync.aligned.m16n8k16.row.col.f32.bf16.bf16.f32 "
                        "{%0,%1,%2,%3}, {%4,%5,%6,%7}, {%8,%9}, {%0,%1,%2,%3};"
                        : "+f"(acc[mt][nt][0]), "+f"(acc[mt][nt][1]),
                          "+f"(acc[mt][nt][2]), "+f"(acc[mt][nt][3])
                        : "r"(af[mt][0]), "r"(af[mt][1]),
                          "r"(af[mt][2]), "r"(af[mt][3]), "r"(b0), "r"(b1));
                }
        }
    };

    for (int iter = 1; iter < 24; iter++) {
        const int t = iter >> 3, k0 = (iter & 7) << 5;
        const uint4* ga = (const uint4*)(Asrc[t] + (size_t)(rowBase + lr) * 256 + k0);
        ra0 = ga[lc]; ra1 = ga[lc + 1];
        const uint4* gb = (const uint4*)(Bsrc[t] + (size_t)(colBase + lr) * 256 + k0);
        rb0 = gb[lc]; rb1 = gb[lc + 1];
        compute();
        __syncthreads();
        *(uint4*)&As[lr][lc * 8] = ra0; *(uint4*)&As[lr][lc * 8 + 8] = ra1;
        *(uint4*)&Bs[lr][lc * 8] = rb0; *(uint4*)&Bs[lr][lc * 8 + 8] = rb1;
        __syncthreads();
    }
    compute();

#pragma unroll
    for (int mt = 0; mt < 4; mt++) {
        int row0 = rowBase + wr * 64 + mt * 16 + (lane >> 2);
#pragma unroll
        for (int h = 0; h < 2; h++) {
            int row = row0 + h * 8;
            float* cr = (row < rowSplit) ? (C0 + (size_t)row * N)
                                         : (C1 + (size_t)(row - rowSplit) * N);
#pragma unroll
            for (int nt = 0; nt < 4; nt++) {
                int col = colBase + wc * 32 + nt * 8 + (lane & 3) * 2;
                float2 bb = *(const float2*)(bias + col);
                float2 v;
                v.x = acc[mt][nt][h * 2 + 0] + bb.x;
                v.y = acc[mt][nt][h * 2 + 1] + bb.y;
                *(float2*)(cr + col) = v;
            }
        }
    }
}

// ---------------- launcher ----------------
extern "C" void kernel_launch(void* const* d_in, const int* in_sizes, int n_in,
                              void* d_out, int out_size)
{
    const float* x_a      = (const float*)d_in[0];
    const float* x_b      = (const float*)d_in[1];
    const float* enc_a_w  = (const float*)d_in[2];
    const float* enc_a_b  = (const float*)d_in[3];
    const float* enc_a_rw = (const float*)d_in[4];
    const float* enc_a_rb = (const float*)d_in[5];
    const float* enc_b_w  = (const float*)d_in[6];
    const float* enc_b_b  = (const float*)d_in[7];
    const float* enc_b_rw = (const float*)d_in[8];
    const float* enc_b_rb = (const float*)d_in[9];
    const float* dec_a_rw = (const float*)d_in[10];
    const float* dec_a_rb = (const float*)d_in[11];
    const float* dec_a_w  = (const float*)d_in[12];
    const float* dec_a_b  = (const float*)d_in[13];
    const float* dec_b_rw = (const float*)d_in[14];
    const float* dec_b_rb = (const float*)d_in[15];
    const float* dec_b_w  = (const float*)d_in[16];
    const float* dec_b_b  = (const float*)d_in[17];
    const float* codebook = (const float*)d_in[18];

    float *ze_a0, *ze_a1, *ze_b0, *ze_b1, *h0a, *h1a, *h0b, *h1b;
    double *zz_a, *zz_b;
    unsigned long long *amin_a, *amin_b;
    __nv_bfloat16 *ah_a, *al_a, *ah_b, *al_b, *wth_a, *wtl_a, *wth_b, *wtl_b;
    cudaGetSymbolAddress((void**)&ze_a0, g_ze_a0);
    cudaGetSymbolAddress((void**)&ze_a1, g_ze_a1);
    cudaGetSymbolAddress((void**)&ze_b0, g_ze_b0);
    cudaGetSymbolAddress((void**)&ze_b1, g_ze_b1);
    cudaGetSymbolAddress((void**)&h0a, g_h0a);
    cudaGetSymbolAddress((void**)&h1a, g_h1a);
    cudaGetSymbolAddress((void**)&h0b, g_h0b);
    cudaGetSymbolAddress((void**)&h1b, g_h1b);
    cudaGetSymbolAddress((void**)&zz_a, g_zz_a);
    cudaGetSymbolAddress((void**)&zz_b, g_zz_b);
    cudaGetSymbolAddress((void**)&amin_a, g_amin_a);
    cudaGetSymbolAddress((void**)&amin_b, g_amin_b);
    cudaGetSymbolAddress((void**)&ah_a, g_ah_a);
    cudaGetSymbolAddress((void**)&al_a, g_al_a);
    cudaGetSymbolAddress((void**)&ah_b, g_ah_b);
    cudaGetSymbolAddress((void**)&al_b, g_al_b);
    cudaGetSymbolAddress((void**)&wth_a, g_wth_a);
    cudaGetSymbolAddress((void**)&wtl_a, g_wtl_a);
    cudaGetSymbolAddress((void**)&wth_b, g_wth_b);
    cudaGetSymbolAddress((void**)&wtl_b, g_wtl_b);

    float* out = (float*)d_out;
    const size_t OFF_ZA = 0;
    const size_t OFF_ZB = (size_t)BATCH * DLAT;
    const size_t OFF_LA = 2 * OFF_ZB;
    const size_t OFF_LB = OFF_LA + BATCH;
    const size_t OFF_RA = OFF_LB + BATCH;
    const size_t OFF_RB = OFF_RA + (size_t)BATCH * DINA;
    const size_t OFF_XA = OFF_RB + (size_t)BATCH * DINB;
    const size_t OFF_XB = OFF_XA + (size_t)BATCH * DINA;

    init_amin_kernel<<<(BATCH + 255) / 256, 256>>>();
    wtsplit_kernel<<<DINA, 256>>>(dec_a_w, wth_a, wtl_a, DINA);
    wtsplit_kernel<<<DINB, 256>>>(dec_b_w, wth_b, wtl_b, DINB);

    // encoder init (A+B batched over z)
    gemm_kernel<true, false><<<dim3(2, BATCH / 64, 2), 256>>>(
        GArgs{x_a, enc_a_w, enc_a_b, ze_a0, DINA},
        GArgs{x_b, enc_b_w, enc_b_b, ze_b0, DINB});
    // encoder res blocks (A+B batched)
    gemm_kernel<true, true><<<dim3(2, BATCH / 64, 2), 256>>>(
        GArgs{ze_a0, enc_a_rw, enc_a_rb, ze_a1, DLAT},
        GArgs{ze_b0, enc_b_rw, enc_b_rb, ze_b1, DLAT});
    gemm_kernel<true, true><<<dim3(2, BATCH / 64, 2), 256>>>(
        GArgs{ze_a1, enc_a_rw + DLAT * DLAT, enc_a_rb + DLAT, ze_a0, DLAT},
        GArgs{ze_b1, enc_b_rw + DLAT * DLAT, enc_b_rb + DLAT, ze_b0, DLAT});

    zz_kernel<<<dim3(BATCH / 8, 2), 256>>>(ze_a0, ze_b0, zz_a, zz_b);

    // VQ argmin (a+b batched)
    vq_argmin_kernel<<<dim3(NCODE / 64, BATCH / 128, 2), 256>>>(
        ze_a0, ze_b0, codebook, zz_a, zz_b, amin_a, amin_b);

    vq_finalize_kernel<<<dim3(BATCH / 8, 2), 256>>>(
        ze_a0, ze_b0, codebook, amin_a, amin_b,
        out + OFF_ZA, out + OFF_ZB, out + OFF_LA, out + OFF_LB);

    const float* Zq = out;
    const int n4 = 2 * BATCH * DLAT / 4;

    // decoder res blocks (decA + decB batched over z), rows = 2B
    gemm_kernel<true, true><<<dim3(2, 2 * BATCH / 64, 2), 256>>>(
        GArgs{Zq, dec_a_rw, dec_a_rb, h1a, DLAT},
        GArgs{Zq, dec_b_rw, dec_b_rb, h1b, DLAT});
    gemm_kernel<true, true><<<dim3(2, 2 * BATCH / 64, 2), 256>>>(
        GArgs{h1a, dec_a_rw + DLAT * DLAT, dec_a_rb + DLAT, h0a, DLAT},
        GArgs{h1b, dec_b_rw + DLAT * DLAT, dec_b_rb + DLAT, h0b, DLAT});

    split_kernel<<<dim3((n4 + 255) / 256, 2), 256>>>(
        h0a, h0b, ah_a, al_a, ah_b, al_b, n4);

    mma_final_kernel<<<dim3(DINA / 128, 2 * BATCH / 128), 256>>>(
        ah_a, al_a, wth_a, wtl_a, dec_a_b,
        out + OFF_RA, out + OFF_XA, BATCH, DINA);
    mma_final_kernel<<<dim3(DINB / 128, 2 * BATCH / 128), 256>>>(
        ah_b, al_b, wth_b, wtl_b, dec_b_b,
        out + OFF_XB, out + OFF_RB, BATCH, DINB);
}

// round 11
// speedup vs baseline: 3.9855x; 1.9963x over previous
#include <cuda_runtime.h>
#include <cuda_bf16.h>
#include <cstdint>
#include <climits>

#define BATCH   8192
#define DINA    4096
#define DINB    2048
#define DLAT    256
#define NCODE   8192
#define BETA_F  0.25f

// ---------------- scratch (static __device__ — no allocation) ----------------
__device__ float g_ze_a0[BATCH * DLAT];
__device__ float g_ze_a1[BATCH * DLAT];
__device__ float g_ze_b0[BATCH * DLAT];
__device__ float g_ze_b1[BATCH * DLAT];
__device__ float g_h1a[2 * BATCH * DLAT];
__device__ float g_h1b[2 * BATCH * DLAT];
__device__ double g_zz_a[BATCH];
__device__ double g_zz_b[BATCH];
__device__ int g_qmax_a[BATCH];
__device__ int g_qmax_b[BATCH];
__device__ int g_win_a[BATCH];
__device__ int g_win_b[BATCH];
__device__ short g_q_a[(size_t)BATCH * NCODE];   // 128 MB
__device__ short g_q_b[(size_t)BATCH * NCODE];   // 128 MB
// bf16 splits
__device__ __nv_bfloat16 g_zh_a[BATCH * DLAT];
__device__ __nv_bfloat16 g_zl_a[BATCH * DLAT];
__device__ __nv_bfloat16 g_zh_b[BATCH * DLAT];
__device__ __nv_bfloat16 g_zl_b[BATCH * DLAT];
__device__ __nv_bfloat16 g_eh[NCODE * DLAT];
__device__ __nv_bfloat16 g_el[NCODE * DLAT];
__device__ __nv_bfloat16 g_zqh[2 * BATCH * DLAT];
__device__ __nv_bfloat16 g_zql[2 * BATCH * DLAT];
__device__ __nv_bfloat16 g_s1h_a[2 * BATCH * DLAT];
__device__ __nv_bfloat16 g_s1l_a[2 * BATCH * DLAT];
__device__ __nv_bfloat16 g_s0h_a[2 * BATCH * DLAT];
__device__ __nv_bfloat16 g_s0l_a[2 * BATCH * DLAT];
__device__ __nv_bfloat16 g_s1h_b[2 * BATCH * DLAT];
__device__ __nv_bfloat16 g_s1l_b[2 * BATCH * DLAT];
__device__ __nv_bfloat16 g_s0h_b[2 * BATCH * DLAT];
__device__ __nv_bfloat16 g_s0l_b[2 * BATCH * DLAT];
__device__ __nv_bfloat16 g_wth_a[DINA * DLAT];
__device__ __nv_bfloat16 g_wtl_a[DINA * DLAT];
__device__ __nv_bfloat16 g_wth_b[DINB * DLAT];
__device__ __nv_bfloat16 g_wtl_b[DINB * DLAT];
__device__ __nv_bfloat16 g_rwth_a[2 * DLAT * DLAT];  // decA res wt splits (2 layers)
__device__ __nv_bfloat16 g_rwtl_a[2 * DLAT * DLAT];
__device__ __nv_bfloat16 g_rwth_b[2 * DLAT * DLAT];
__device__ __nv_bfloat16 g_rwtl_b[2 * DLAT * DLAT];

__device__ __forceinline__ uint32_t smem_u32(const void* p) {
    uint32_t a;
    asm("{ .reg .u64 t; cvta.to.shared.u64 t, %1; cvt.u32.u64 %0, t; }"
        : "=r"(a) : "l"(p));
    return a;
}
__device__ __forceinline__ void cp16(uint32_t s, const void* g) {
    asm volatile("cp.async.cg.shared.global [%0], [%1], 16;" :: "r"(s), "l"(g));
}

// ---------------- small helpers ----------------
__global__ void init_qmax_kernel() {
    int i = blockIdx.x * blockDim.x + threadIdx.x;
    if (i < BATCH) { g_qmax_a[i] = INT_MIN; g_qmax_b[i] = INT_MIN; }
}

__global__ void zz_kernel(const float* __restrict__ Z0, const float* __restrict__ Z1,
                          double* __restrict__ zz0, double* __restrict__ zz1) {
    const float* Z = blockIdx.y ? Z1 : Z0;
    double* zz = blockIdx.y ? zz1 : zz0;
    int row  = blockIdx.x * 8 + (threadIdx.x >> 5);
    int lane = threadIdx.x & 31;
    const float4* zp = reinterpret_cast<const float4*>(Z) + (size_t)row * (DLAT / 4);
    double s = 0.0;
#pragma unroll
    for (int t = 0; t < 2; t++) {
        float4 v = zp[lane + 32 * t];
        s += (double)v.x * v.x + (double)v.y * v.y
           + (double)v.z * v.z + (double)v.w * v.w;
    }
#pragma unroll
    for (int o = 16; o; o >>= 1) s += __shfl_down_sync(0xffffffffu, s, o);
    if (lane == 0) zz[row] = s;
}

// elementwise bf16 hi/lo split (float4-vectorized)
__global__ void split1_kernel(const float* __restrict__ x,
                              __nv_bfloat16* __restrict__ hi,
                              __nv_bfloat16* __restrict__ lo, int n4)
{
    int i = blockIdx.x * blockDim.x + threadIdx.x;
    if (i >= n4) return;
    float4 v = ((const float4*)x)[i];
    __nv_bfloat16 hx = __float2bfloat16(v.x), hy = __float2bfloat16(v.y);
    __nv_bfloat16 hz = __float2bfloat16(v.z), hw = __float2bfloat16(v.w);
    __nv_bfloat162 h01; h01.x = hx; h01.y = hy;
    __nv_bfloat162 h23; h23.x = hz; h23.y = hw;
    __nv_bfloat162 l01, l23;
    l01.x = __float2bfloat16(v.x - __bfloat162float(hx));
    l01.y = __float2bfloat16(v.y - __bfloat162float(hy));
    l23.x = __float2bfloat16(v.z - __bfloat162float(hz));
    l23.y = __float2bfloat16(v.w - __bfloat162float(hw));
    ((__nv_bfloat162*)hi)[i * 2 + 0] = h01;
    ((__nv_bfloat162*)hi)[i * 2 + 1] = h23;
    ((__nv_bfloat162*)lo)[i * 2 + 0] = l01;
    ((__nv_bfloat162*)lo)[i * 2 + 1] = l23;
}

// transpose W [K=256, N] -> Wt [N, 256] with bf16 hi/lo split
__global__ void wtsplit_kernel(const float* __restrict__ W,
                               __nv_bfloat16* __restrict__ th,
                               __nv_bfloat16* __restrict__ tl, int N)
{
    int i = blockIdx.x * blockDim.x + threadIdx.x;
    int n = i >> 8, k = i & 255;
    float x = W[(size_t)k * N + n];
    __nv_bfloat16 h = __float2bfloat16(x);
    th[i] = h;
    tl[i] = __float2bfloat16(x - __bfloat162float(h));
}

// ---------------- SIMT fused GEMM (exact fp32 chain — encoders) -------------
struct GArgs { const float* A; const float* W; const float* bias; float* C; int K; };

template<bool RELU, bool RESID>
__global__ __launch_bounds__(256, 3)
void gemm_kernel(GArgs g0, GArgs g1)
{
    const GArgs g = blockIdx.z ? g1 : g0;
    const int K = g.K;
    __shared__ float As[2][8][68];
    __shared__ float Bs[2][8][128];
    const int tid = threadIdx.x;
    const int tx = tid & 15, ty = tid >> 4;
    const int rowBase = blockIdx.y * 64;
    const int colBase = blockIdx.x * 128;

    const int ar = tid >> 1, ac4 = (tid & 1) * 4;
    const bool aAct = tid < 128;
    const float* Ap = aAct ? (g.A + (size_t)(rowBase + ar) * K + ac4) : g.A;
    const int br = tid >> 5, bc = (tid & 31) * 4;
    const float* Wp = g.W + (size_t)br * 256 + colBase + bc;
    const uint32_t bs0 = smem_u32(&Bs[0][br][bc]);
    const uint32_t bs1 = smem_u32(&Bs[1][br][bc]);

    float acc[4][8];
#pragma unroll
    for (int i = 0; i < 4; i++)
#pragma unroll
        for (int j = 0; j < 8; j++) acc[i][j] = 0.f;

    float4 av = make_float4(0.f, 0.f, 0.f, 0.f);
    if (aAct) av = *(const float4*)Ap;
    cp16(bs0, Wp);
    asm volatile("cp.async.commit_group;");
    if (aAct) {
        As[0][ac4 + 0][ar] = av.x; As[0][ac4 + 1][ar] = av.y;
        As[0][ac4 + 2][ar] = av.z; As[0][ac4 + 3][ar] = av.w;
    }
    asm volatile("cp.async.wait_group 0;");
    __syncthreads();

    const int nIter = K >> 3;
    int buf = 0;
#pragma unroll 1
    for (int i = 0; i < nIter; i++) {
        const bool more = (i + 1 < nIter);
        if (more) {
            if (aAct) av = *(const float4*)(Ap + (size_t)(i + 1) * 8);
            cp16(buf ? bs0 : bs1, Wp + (size_t)(i + 1) * 8 * 256);
            asm volatile("cp.async.commit_group;");
        }
#pragma unroll
        for (int kk = 0; kk < 8; kk++) {
            float4 a4 = *(const float4*)&As[buf][kk][ty * 4];
            float4 b0 = *(const float4*)&Bs[buf][kk][tx * 4];
            float4 b1 = *(const float4*)&Bs[buf][kk][tx * 4 + 64];
            float a[4] = {a4.x, a4.y, a4.z, a4.w};
            float b[8] = {b0.x, b0.y, b0.z, b0.w, b1.x, b1.y, b1.z, b1.w};
#pragma unroll
            for (int i2 = 0; i2 < 4; i2++)
#pragma unroll
                for (int j = 0; j < 8; j++)
                    acc[i2][j] = fmaf(a[i2], b[j], acc[i2][j]);
        }
        if (more) {
            if (aAct) {
                int nb = buf ^ 1;
                As[nb][ac4 + 0][ar] = av.x; As[nb][ac4 + 1][ar] = av.y;
                As[nb][ac4 + 2][ar] = av.z; As[nb][ac4 + 3][ar] = av.w;
            }
            asm volatile("cp.async.wait_group 0;");
        }
        __syncthreads();
        buf ^= 1;
    }

#pragma unroll
    for (int i2 = 0; i2 < 4; i2++) {
        int row = rowBase + ty * 4 + i2;
        float* cr = g.C + (size_t)row * 256;
        const float* rr = RESID ? (g.A + (size_t)row * 256) : nullptr;
#pragma unroll
        for (int gg = 0; gg < 2; gg++) {
            int col = colBase + tx * 4 + gg * 64;
            float4 bb = *(const float4*)(g.bias + col);
            float4 v;
            v.x = acc[i2][gg * 4 + 0] + bb.x;
            v.y = acc[i2][gg * 4 + 1] + bb.y;
            v.z = acc[i2][gg * 4 + 2] + bb.z;
            v.w = acc[i2][gg * 4 + 3] + bb.w;
            if (RELU) {
                v.x = fmaxf(v.x, 0.f); v.y = fmaxf(v.y, 0.f);
                v.z = fmaxf(v.z, 0.f); v.w = fmaxf(v.w, 0.f);
            }
            if (RESID) {
                float4 rv = *(const float4*)(rr + col);
                v.x += rv.x; v.y += rv.y; v.z += rv.z; v.w += rv.w;
            }
            *(float4*)(cr + col) = v;
        }
    }
}

// =================== bf16 3-term mma core (macro-shared) ====================
// Computes fp32 acc of (Ah+Al)@(Bh+Bl)^T (Al*Bl dropped) for a 128x128 tile.
// As/Bs [128][40] stride-40 layout, 8 warps 2x4, m16n8k16.

#define MMA_CORE_BODY(AhP, AlP, BhP, BlP)                                       \
    const int lr = tid >> 1;                                                    \
    const int lc = (tid & 1) * 2;                                               \
    const __nv_bfloat16* Asrc[3] = {AhP, AhP, AlP};                             \
    const __nv_bfloat16* Bsrc[3] = {BhP, BlP, BhP};                             \
    float acc[4][4][4];                                                         \
    _Pragma("unroll")                                                           \
    for (int m = 0; m < 4; m++)                                                 \
        _Pragma("unroll")                                                       \
        for (int n = 0; n < 4; n++)                                             \
            _Pragma("unroll")                                                   \
            for (int c = 0; c < 4; c++) acc[m][n][c] = 0.f;                     \
    const uint32_t aAddr = smem_u32(&As[wr * 64 + (lane & 15)][(lane >> 4) * 8]); \
    const uint32_t bAddr = smem_u32(                                            \
        &Bs[wc * 32 + (lane & 7) + ((lane >> 4) & 1) * 8][((lane >> 3) & 1) * 8]); \
    uint4 ra0, ra1, rb0, rb1;                                                   \
    {                                                                           \
        const uint4* ga = (const uint4*)(Asrc[0] + (size_t)(rowBase + lr) * 256); \
        ra0 = ga[lc]; ra1 = ga[lc + 1];                                         \
        const uint4* gb = (const uint4*)(Bsrc[0] + (size_t)(colBase + lr) * 256); \
        rb0 = gb[lc]; rb1 = gb[lc + 1];                                         \
    }                                                                           \
    *(uint4*)&As[lr][lc * 8] = ra0; *(uint4*)&As[lr][lc * 8 + 8] = ra1;         \
    *(uint4*)&Bs[lr][lc * 8] = rb0; *(uint4*)&Bs[lr][lc * 8 + 8] = rb1;         \
    __syncthreads();                                                            \
    auto compute = [&]() {                                                      \
        _Pragma("unroll")                                                       \
        for (int ss = 0; ss < 2; ss++) {                                        \
            uint32_t af[4][4];                                                  \
            _Pragma("unroll")                                                   \
            for (int mt = 0; mt < 4; mt++) {                                    \
                uint32_t addr = aAddr + mt * 16 * 80 + ss * 32;                 \
                asm volatile(                                                   \
                    "ldmatrix.sync.aligned.m8n8.x4.shared.b16 {%0,%1,%2,%3}, [%4];" \
                    : "=r"(af[mt][0]), "=r"(af[mt][1]),                         \
                      "=r"(af[mt][2]), "=r"(af[mt][3]) : "r"(addr));            \
            }                                                                   \
            uint32_t bfr[2][4];                                                 \
            _Pragma("unroll")                                                   \
            for (int bp = 0; bp < 2; bp++) {                                    \
                uint32_t addr = bAddr + bp * 16 * 80 + ss * 32;                 \
                asm volatile(                                                   \
                    "ldmatrix.sync.aligned.m8n8.x4.shared.b16 {%0,%1,%2,%3}, [%4];" \
                    : "=r"(bfr[bp][0]), "=r"(bfr[bp][1]),                       \
                      "=r"(bfr[bp][2]), "=r"(bfr[bp][3]) : "r"(addr));          \
            }                                                                   \
            _Pragma("unroll")                                                   \
            for (int mt = 0; mt < 4; mt++)                                      \
                _Pragma("unroll")                                               \
                for (int nt = 0; nt < 4; nt++) {                                \
                    uint32_t b0 = bfr[nt >> 1][(nt & 1) * 2 + 0];               \
                    uint32_t b1 = bfr[nt >> 1][(nt & 1) * 2 + 1];               \
                    asm volatile(                                               \
                        "mma.sync.aligned.m16n8k16.row.col.f32.bf16.bf16.f32 "  \
                        "{%0,%1,%2,%3}, {%4,%5,%6,%7}, {%8,%9}, {%0,%1,%2,%3};" \
                        : "+f"(acc[mt][nt][0]), "+f"(acc[mt][nt][1]),           \
                          "+f"(acc[mt][nt][2]), "+f"(acc[mt][nt][3])            \
                        : "r"(af[mt][0]), "r"(af[mt][1]),                       \
                          "r"(af[mt][2]), "r"(af[mt][3]), "r"(b0), "r"(b1));    \
                }                                                               \
        }                                                                       \
    };                                                                          \
    for (int iter = 1; iter < 24; iter++) {                                     \
        const int t = iter >> 3, k0 = (iter & 7) << 5;                          \
        const uint4* ga = (const uint4*)(Asrc[t] + (size_t)(rowBase + lr) * 256 + k0); \
        ra0 = ga[lc]; ra1 = ga[lc + 1];                                         \
        const uint4* gb = (const uint4*)(Bsrc[t] + (size_t)(colBase + lr) * 256 + k0); \
        rb0 = gb[lc]; rb1 = gb[lc + 1];                                         \
        compute();                                                              \
        __syncthreads();                                                        \
        *(uint4*)&As[lr][lc * 8] = ra0; *(uint4*)&As[lr][lc * 8 + 8] = ra1;     \
        *(uint4*)&Bs[lr][lc * 8] = rb0; *(uint4*)&Bs[lr][lc * 8 + 8] = rb1;     \
        __syncthreads();                                                        \
    }                                                                           \
    compute();

// ---------------- decoder FINAL: C = split(A)@split(W)^T + bias -------------
__global__ __launch_bounds__(256, 2)
void mma_final_kernel(const __nv_bfloat16* __restrict__ Ah,
                      const __nv_bfloat16* __restrict__ Al,
                      const __nv_bfloat16* __restrict__ Bh,
                      const __nv_bfloat16* __restrict__ Bl,
                      const float* __restrict__ bias,
                      float* __restrict__ C0, float* __restrict__ C1,
                      int rowSplit, int N)
{
    __shared__ __align__(16) __nv_bfloat16 As[128][40];
    __shared__ __align__(16) __nv_bfloat16 Bs[128][40];
    const int tid = threadIdx.x;
    const int wid = tid >> 5, lane = tid & 31;
    const int wr = wid >> 2, wc = wid & 3;
    const int rowBase = blockIdx.y * 128;
    const int colBase = blockIdx.x * 128;

    MMA_CORE_BODY(Ah, Al, Bh, Bl)

#pragma unroll
    for (int mt = 0; mt < 4; mt++) {
        int row0 = rowBase + wr * 64 + mt * 16 + (lane >> 2);
#pragma unroll
        for (int h = 0; h < 2; h++) {
            int row = row0 + h * 8;
            float* cr = (row < rowSplit) ? (C0 + (size_t)row * N)
                                         : (C1 + (size_t)(row - rowSplit) * N);
#pragma unroll
            for (int nt = 0; nt < 4; nt++) {
                int col = colBase + wc * 32 + nt * 8 + (lane & 3) * 2;
                float2 bb = *(const float2*)(bias + col);
                float2 v;
                v.x = acc[mt][nt][h * 2 + 0] + bb.x;
                v.y = acc[mt][nt][h * 2 + 1] + bb.y;
                *(float2*)(cr + col) = v;
            }
        }
    }
}

// ---------------- decoder RES block: C = A + relu(split(A)@Wt + b) ----------
// writes fp32 C (optional) + fused bf16 hi/lo split of C.
template<bool WF32>
__global__ __launch_bounds__(256, 2)
void mma_res_kernel(const float* __restrict__ Af,
                    const __nv_bfloat16* __restrict__ Ah,
                    const __nv_bfloat16* __restrict__ Al,
                    const __nv_bfloat16* __restrict__ Bh,
                    const __nv_bfloat16* __restrict__ Bl,
                    const float* __restrict__ bias,
                    float* __restrict__ Cf,
                    __nv_bfloat16* __restrict__ Ch,
                    __nv_bfloat16* __restrict__ Cl)
{
    __shared__ __align__(16) __nv_bfloat16 As[128][40];
    __shared__ __align__(16) __nv_bfloat16 Bs[128][40];
    const int tid = threadIdx.x;
    const int wid = tid >> 5, lane = tid & 31;
    const int wr = wid >> 2, wc = wid & 3;
    const int rowBase = blockIdx.y * 128;
    const int colBase = blockIdx.x * 128;

    MMA_CORE_BODY(Ah, Al, Bh, Bl)

#pragma unroll
    for (int mt = 0; mt < 4; mt++) {
        int row0 = rowBase + wr * 64 + mt * 16 + (lane >> 2);
#pragma unroll
        for (int h = 0; h < 2; h++) {
            int row = row0 + h * 8;
#pragma unroll
            for (int nt = 0; nt < 4; nt++) {
                int col = colBase + wc * 32 + nt * 8 + (lane & 3) * 2;
                size_t off = (size_t)row * 256 + col;
                float2 bb = *(const float2*)(bias + col);
                float2 rv = *(const float2*)(Af + off);
                float vx = rv.x + fmaxf(acc[mt][nt][h * 2 + 0] + bb.x, 0.f);
                float vy = rv.y + fmaxf(acc[mt][nt][h * 2 + 1] + bb.y, 0.f);
                if (WF32) { float2 o; o.x = vx; o.y = vy; *(float2*)(Cf + off) = o; }
                __nv_bfloat162 hh, ll;
                hh.x = __float2bfloat16(vx); hh.y = __float2bfloat16(vy);
                ll.x = __float2bfloat16(vx - __bfloat162float(hh.x));
                ll.y = __float2bfloat16(vy - __bfloat162float(hh.y));
                *(__nv_bfloat162*)(Ch + off) = hh;
                *(__nv_bfloat162*)(Cl + off) = ll;
            }
        }
    }
}

// ---------------- VQ phase 1: t~ = 2*z.e via 3-term mma; q16 + row max ------
__global__ __launch_bounds__(256, 2)
void vq_mma_kernel()
{
    __shared__ __align__(16) __nv_bfloat16 As[128][40];
    __shared__ __align__(16) __nv_bfloat16 Bs[128][40];
    const int tid = threadIdx.x;
    const int wid = tid >> 5, lane = tid & 31;
    const int wr = wid >> 2, wc = wid & 3;
    const int rowBase = blockIdx.y * 128;
    const int colBase = blockIdx.x * 128;
    const int bz = blockIdx.z;
    const __nv_bfloat16* Zh = bz ? g_zh_b : g_zh_a;
    const __nv_bfloat16* Zl = bz ? g_zl_b : g_zl_a;
    short* Q = bz ? g_q_b : g_q_a;
    int* qmax = bz ? g_qmax_b : g_qmax_a;

    MMA_CORE_BODY(Zh, Zl, g_eh, g_el)

#pragma unroll
    for (int mt = 0; mt < 4; mt++) {
        int row0 = rowBase + wr * 64 + mt * 16 + (lane >> 2);
#pragma unroll
        for (int h = 0; h < 2; h++) {
            int row = row0 + h * 8;
            int mq = INT_MIN;
#pragma unroll
            for (int nt = 0; nt < 4; nt++) {
                int col = colBase + wc * 32 + nt * 8 + (lane & 3) * 2;
                float t0 = 2.f * acc[mt][nt][h * 2 + 0];
                float t1 = 2.f * acc[mt][nt][h * 2 + 1];
                int q0 = __float2int_rn(t0 * 524288.f);   // 2^19
                int q1 = __float2int_rn(t1 * 524288.f);
                q0 = max(-32000, min(32000, q0));
                q1 = max(-32000, min(32000, q1));
                mq = max(mq, max(q0, q1));
                short2 sv; sv.x = (short)q0; sv.y = (short)q1;
                *(short2*)(Q + (size_t)row * NCODE + col) = sv;
            }
            mq = max(mq, __shfl_xor_sync(0xffffffffu, mq, 1));
            mq = max(mq, __shfl_xor_sync(0xffffffffu, mq, 2));
            if ((lane & 3) == 0) atomicMax(&qmax[row], mq);
        }
    }
}

// ---------------- VQ phase 2: candidate select + exact chain recompute ------
__global__ __launch_bounds__(256)
void vq_select_kernel(const float* __restrict__ Z0, const float* __restrict__ Z1,
                      const float* __restrict__ E)
{
    const int row = blockIdx.x, bz = blockIdx.y;
    const int tid = threadIdx.x;
    const float* Zr = (bz ? Z1 : Z0) + (size_t)row * DLAT;
    const short* Q = (bz ? g_q_b : g_q_a) + (size_t)row * NCODE;
    const int thr = (bz ? g_qmax_b : g_qmax_a)[row] - 48;
    const double zz = (bz ? g_zz_b : g_zz_a)[row];

    __shared__ float zs[DLAT];
    __shared__ int cnt;
    __shared__ int cand[128];
    __shared__ unsigned long long best;
    zs[tid] = Zr[tid];
    if (tid == 0) { cnt = 0; best = ~0ull; }
    __syncthreads();

    const short2* Q2 = (const short2*)Q;
#pragma unroll
    for (int it = 0; it < 16; it++) {
        int i2 = tid + it * 256;
        short2 v = Q2[i2];
        if (v.x >= thr) { int p = atomicAdd(&cnt, 1); if (p < 128) cand[p] = i2 * 2; }
        if (v.y >= thr) { int p = atomicAdd(&cnt, 1); if (p < 128) cand[p] = i2 * 2 + 1; }
    }
    __syncthreads();

    int n = min(cnt, 128);
    if (tid < n) {
        int c = cand[tid];
        const float* e = E + (size_t)c * DLAT;
        float accv = 0.f;
#pragma unroll 8
        for (int k = 0; k < DLAT; k++) accv = fmaf(zs[k], e[k], accv);
        double t = 2.0 * (double)accv;                // fl32 doubling exact
        double d = zz - t;
        long long db = __double_as_longlong(d);
        int ebias = (int)((db >> 52) & 0x7ff);
        double cell = __longlong_as_double((long long)(ebias - 23) << 52);
        double r = cell * rint(t / cell);
        float rf = (float)r;
        unsigned u = __float_as_uint(rf);
        u = (u & 0x80000000u) ? ~u : (u | 0x80000000u);
        unsigned long long key = ((unsigned long long)(~u) << 32) | (unsigned)c;
        atomicMin(&best, key);
    }
    __syncthreads();
    if (tid == 0) (bz ? g_win_b : g_win_a)[row] = (int)(best & 0xffffffffull);
}

// ---------------- VQ finalize: zq + loss + fused zq bf16 split --------------
__global__ void vq_finalize_kernel(const float* __restrict__ Z0, const float* __restrict__ Z1,
                                   const float* __restrict__ E,
                                   float* __restrict__ zq0, float* __restrict__ zq1,
                                   float* __restrict__ ls0, float* __restrict__ ls1)
{
    const int bz = blockIdx.y;
    const float* Z = bz ? Z1 : Z0;
    float* zq = bz ? zq1 : zq0;
    float* loss = bz ? ls1 : ls0;
    int row  = blockIdx.x * 8 + (threadIdx.x >> 5);
    int lane = threadIdx.x & 31;
    int idx  = (bz ? g_win_b : g_win_a)[row];
    const float4* zp = reinterpret_cast<const float4*>(Z) + (size_t)row * (DLAT / 4);
    const float4* ep = reinterpret_cast<const float4*>(E) + (size_t)idx * (DLAT / 4);
    float4* qp = reinterpret_cast<float4*>(zq) + (size_t)row * (DLAT / 4);
    size_t srow = ((size_t)bz * BATCH + row) * DLAT;  // Zq global row for splits
    float s = 0.f;
#pragma unroll
    for (int t = 0; t < 2; t++) {
        float4 z = zp[lane + 32 * t], e = ep[lane + 32 * t];
        float dx = e.x - z.x, dy = e.y - z.y, dz = e.z - z.z, dw = e.w - z.w;
        float4 o;
        o.x = z.x + dx; o.y = z.y + dy; o.z = z.z + dz; o.w = z.w + dw;
        qp[lane + 32 * t] = o;
        // fused bf16 split of zq
        float vv[4] = {o.x, o.y, o.z, o.w};
#pragma unroll
        for (int p = 0; p < 2; p++) {
            __nv_bfloat162 hh, ll;
            hh.x = __float2bfloat16(vv[p * 2 + 0]);
            hh.y = __float2bfloat16(vv[p * 2 + 1]);
            ll.x = __float2bfloat16(vv[p * 2 + 0] - __bfloat162float(hh.x));
            ll.y = __float2bfloat16(vv[p * 2 + 1] - __bfloat162float(hh.y));
            size_t eo = srow + (lane + 32 * t) * 4 + p * 2;
            *(__nv_bfloat162*)(g_zqh + eo) = hh;
            *(__nv_bfloat162*)(g_zql + eo) = ll;
        }
        s += dx * dx + dy * dy + dz * dz + dw * dw;
    }
#pragma unroll
    for (int o = 16; o; o >>= 1) s += __shfl_down_sync(0xffffffffu, s, o);
    if (lane == 0) loss[row] = s + BETA_F * s;
}

// ---------------- launcher ----------------
extern "C" void kernel_launch(void* const* d_in, const int* in_sizes, int n_in,
                              void* d_out, int out_size)
{
    const float* x_a      = (const float*)d_in[0];
    const float* x_b      = (const float*)d_in[1];
    const float* enc_a_w  = (const float*)d_in[2];
    const float* enc_a_b  = (const float*)d_in[3];
    const float* enc_a_rw = (const float*)d_in[4];
    const float* enc_a_rb = (const float*)d_in[5];
    const float* enc_b_w  = (const float*)d_in[6];
    const float* enc_b_b  = (const float*)d_in[7];
    const float* enc_b_rw = (const float*)d_in[8];
    const float* enc_b_rb = (const float*)d_in[9];
    const float* dec_a_rw = (const float*)d_in[10];
    const float* dec_a_rb = (const float*)d_in[11];
    const float* dec_a_w  = (const float*)d_in[12];
    const float* dec_a_b  = (const float*)d_in[13];
    const float* dec_b_rw = (const float*)d_in[14];
    const float* dec_b_rb = (const float*)d_in[15];
    const float* dec_b_w  = (const float*)d_in[16];
    const float* dec_b_b  = (const float*)d_in[17];
    const float* codebook = (const float*)d_in[18];

    float *ze_a0, *ze_a1, *ze_b0, *ze_b1, *h1a, *h1b;
    double *zz_a, *zz_b;
    __nv_bfloat16 *zh_a, *zl_a, *zh_b, *zl_b, *eh, *el, *zqh, *zql;
    __nv_bfloat16 *s1h_a, *s1l_a, *s0h_a, *s0l_a, *s1h_b, *s1l_b, *s0h_b, *s0l_b;
    __nv_bfloat16 *wth_a, *wtl_a, *wth_b, *wtl_b;
    __nv_bfloat16 *rwth_a, *rwtl_a, *rwth_b, *rwtl_b;
    cudaGetSymbolAddress((void**)&ze_a0, g_ze_a0);
    cudaGetSymbolAddress((void**)&ze_a1, g_ze_a1);
    cudaGetSymbolAddress((void**)&ze_b0, g_ze_b0);
    cudaGetSymbolAddress((void**)&ze_b1, g_ze_b1);
    cudaGetSymbolAddress((void**)&h1a, g_h1a);
    cudaGetSymbolAddress((void**)&h1b, g_h1b);
    cudaGetSymbolAddress((void**)&zz_a, g_zz_a);
    cudaGetSymbolAddress((void**)&zz_b, g_zz_b);
    cudaGetSymbolAddress((void**)&zh_a, g_zh_a);
    cudaGetSymbolAddress((void**)&zl_a, g_zl_a);
    cudaGetSymbolAddress((void**)&zh_b, g_zh_b);
    cudaGetSymbolAddress((void**)&zl_b, g_zl_b);
    cudaGetSymbolAddress((void**)&eh, g_eh);
    cudaGetSymbolAddress((void**)&el, g_el);
    cudaGetSymbolAddress((void**)&zqh, g_zqh);
    cudaGetSymbolAddress((void**)&zql, g_zql);
    cudaGetSymbolAddress((void**)&s1h_a, g_s1h_a);
    cudaGetSymbolAddress((void**)&s1l_a, g_s1l_a);
    cudaGetSymbolAddress((void**)&s0h_a, g_s0h_a);
    cudaGetSymbolAddress((void**)&s0l_a, g_s0l_a);
    cudaGetSymbolAddress((void**)&s1h_b, g_s1h_b);
    cudaGetSymbolAddress((void**)&s1l_b, g_s1l_b);
    cudaGetSymbolAddress((void**)&s0h_b, g_s0h_b);
    cudaGetSymbolAddress((void**)&s0l_b, g_s0l_b);
    cudaGetSymbolAddress((void**)&wth_a, g_wth_a);
    cudaGetSymbolAddress((void**)&wtl_a, g_wtl_a);
    cudaGetSymbolAddress((void**)&wth_b, g_wth_b);
    cudaGetSymbolAddress((void**)&wtl_b, g_wtl_b);
    cudaGetSymbolAddress((void**)&rwth_a, g_rwth_a);
    cudaGetSymbolAddress((void**)&rwtl_a, g_rwtl_a);
    cudaGetSymbolAddress((void**)&rwth_b, g_rwth_b);
    cudaGetSymbolAddress((void**)&rwtl_b, g_rwtl_b);

    float* out = (float*)d_out;
    const size_t OFF_ZA = 0;
    const size_t OFF_ZB = (size_t)BATCH * DLAT;
    const size_t OFF_LA = 2 * OFF_ZB;
    const size_t OFF_LB = OFF_LA + BATCH;
    const size_t OFF_RA = OFF_LB + BATCH;
    const size_t OFF_RB = OFF_RA + (size_t)BATCH * DINA;
    const size_t OFF_XA = OFF_RB + (size_t)BATCH * DINB;
    const size_t OFF_XB = OFF_XA + (size_t)BATCH * DINA;

    init_qmax_kernel<<<(BATCH + 255) / 256, 256>>>();
    // weight transpose+splits (inputs only)
    wtsplit_kernel<<<DINA, 256>>>(dec_a_w, wth_a, wtl_a, DINA);
    wtsplit_kernel<<<DINB, 256>>>(dec_b_w, wth_b, wtl_b, DINB);
    wtsplit_kernel<<<DLAT, 256>>>(dec_a_rw, rwth_a, rwtl_a, DLAT);
    wtsplit_kernel<<<DLAT, 256>>>(dec_a_rw + DLAT * DLAT, rwth_a + DLAT * DLAT,
                                  rwtl_a + DLAT * DLAT, DLAT);
    wtsplit_kernel<<<DLAT, 256>>>(dec_b_rw, rwth_b, rwtl_b, DLAT);
    wtsplit_kernel<<<DLAT, 256>>>(dec_b_rw + DLAT * DLAT, rwth_b + DLAT * DLAT,
                                  rwtl_b + DLAT * DLAT, DLAT);
    // codebook split
    split1_kernel<<<(NCODE * DLAT / 4 + 255) / 256, 256>>>(codebook, eh, el,
                                                           NCODE * DLAT / 4);

    // encoders (exact fp32, argmin-critical)
    gemm_kernel<true, false><<<dim3(2, BATCH / 64, 2), 256>>>(
        GArgs{x_a, enc_a_w, enc_a_b, ze_a0, DINA},
        GArgs{x_b, enc_b_w, enc_b_b, ze_b0, DINB});
    gemm_kernel<true, true><<<dim3(2, BATCH / 64, 2), 256>>>(
        GArgs{ze_a0, enc_a_rw, enc_a_rb, ze_a1, DLAT},
        GArgs{ze_b0, enc_b_rw, enc_b_rb, ze_b1, DLAT});
    gemm_kernel<true, true><<<dim3(2, BATCH / 64, 2), 256>>>(
        GArgs{ze_a1, enc_a_rw + DLAT * DLAT, enc_a_rb + DLAT, ze_a0, DLAT},
        GArgs{ze_b1, enc_b_rw + DLAT * DLAT, enc_b_rb + DLAT, ze_b0, DLAT});

    zz_kernel<<<dim3(BATCH / 8, 2), 256>>>(ze_a0, ze_b0, zz_a, zz_b);
    split1_kernel<<<(BATCH * DLAT / 4 + 255) / 256, 256>>>(ze_a0, zh_a, zl_a,
                                                           BATCH * DLAT / 4);
    split1_kernel<<<(BATCH * DLAT / 4 + 255) / 256, 256>>>(ze_b0, zh_b, zl_b,
                                                           BATCH * DLAT / 4);

    // VQ: tensor-core approx scores, then exact-chain candidate resolve
    vq_mma_kernel<<<dim3(NCODE / 128, BATCH / 128, 2), 256>>>();
    vq_select_kernel<<<dim3(BATCH, 2), 256>>>(ze_a0, ze_b0, codebook);

    vq_finalize_kernel<<<dim3(BATCH / 8, 2), 256>>>(
        ze_a0, ze_b0, codebook,
        out + OFF_ZA, out + OFF_ZB, out + OFF_LA, out + OFF_LB);

    const float* Zq = out;

    // decoder res blocks on tensor cores (bf16 3-term, fused split epilogue)
    mma_res_kernel<true><<<dim3(2, 2 * BATCH / 128), 256>>>(
        Zq, zqh, zql, rwth_a, rwtl_a, dec_a_rb, h1a, s1h_a, s1l_a);
    mma_res_kernel<true><<<dim3(2, 2 * BATCH / 128), 256>>>(
        Zq, zqh, zql, rwth_b, rwtl_b, dec_b_rb, h1b, s1h_b, s1l_b);
    mma_res_kernel<false><<<dim3(2, 2 * BATCH / 128), 256>>>(
        h1a, s1h_a, s1l_a, rwth_a + DLAT * DLAT, rwtl_a + DLAT * DLAT,
        dec_a_rb + DLAT, nullptr, s0h_a, s0l_a);
    mma_res_kernel<false><<<dim3(2, 2 * BATCH / 128), 256>>>(
        h1b, s1h_b, s1l_b, rwth_b + DLAT * DLAT, rwtl_b + DLAT * DLAT,
        dec_b_rb + DLAT, nullptr, s0h_b, s0l_b);

    // decoder finals
    mma_final_kernel<<<dim3(DINA / 128, 2 * BATCH / 128), 256>>>(
        s0h_a, s0l_a, wth_a, wtl_a, dec_a_b,
        out + OFF_RA, out + OFF_XA, BATCH, DINA);
    mma_final_kernel<<<dim3(DINB / 128, 2 * BATCH / 128), 256>>>(
        s0h_b, s0l_b, wth_b, wtl_b, dec_b_b,
        out + OFF_XB, out + OFF_RB, BATCH, DINB);
}